// round 12
// baseline (speedup 1.0000x reference)
#include <cuda_runtime.h>
#include <cuda_bf16.h>
#include <cuda_fp16.h>
#include <math.h>
#include <stdint.h>

// ---------------- problem constants ----------------
#define BB 4
#define SS 1024
#define LL 12
#define DD 768
#define HH 12
#define DKK 64
#define DFF 3072
#define VV 50257
#define NTOK (BB*SS)          // 4096
#define KPD (DD/2)            // 384
#define KPF (DFF/2)           // 1536

// ---------------- scratch (device globals; no allocs allowed) --------------
__device__ float g_x [(size_t)NTOK * DD];
__device__ float g_v [(size_t)NTOK * DD];
__device__ unsigned g_q16 [(size_t)NTOK * KPD];
__device__ unsigned g_k16 [(size_t)NTOK * KPD];
__device__ unsigned g_h16 [(size_t)NTOK * KPD];
__device__ unsigned g_tmp16[(size_t)NTOK * KPD];
__device__ unsigned g_ff16 [(size_t)NTOK * KPF];
__device__ unsigned g_vph [(size_t)BB * HH * DKK * (SS/2)];
__device__ unsigned g_vpl [(size_t)BB * HH * DKK * (SS/2)];
// packed fp16 weights, K-major: [L][N][K/2] half2 words
__device__ unsigned g_wq16 [(size_t)LL * DD * KPD];
__device__ unsigned g_wk16 [(size_t)LL * DD * KPD];
__device__ unsigned g_wv16 [(size_t)LL * DD * KPD];
__device__ unsigned g_wo16 [(size_t)LL * DD * KPD];
__device__ unsigned g_fc116[(size_t)LL * DFF * KPD];
__device__ unsigned g_fc216[(size_t)LL * DD * KPF];
__device__ unsigned g_wte16[(size_t)VV * KPD];

// ---------------- helpers ----------------
__device__ __forceinline__ uint32_t smem_u32(const void* p) {
    uint32_t a;
    asm("{ .reg .u64 t; cvta.to.shared.u64 t, %1; cvt.u32.u64 %0, t; }"
        : "=r"(a) : "l"(p));
    return a;
}
__device__ __forceinline__ void mma16(float* d, const unsigned* a, const unsigned* b) {
    asm volatile(
        "mma.sync.aligned.m16n8k16.row.col.f32.f16.f16.f32 "
        "{%0,%1,%2,%3},{%4,%5,%6,%7},{%8,%9},{%0,%1,%2,%3};"
        : "+f"(d[0]), "+f"(d[1]), "+f"(d[2]), "+f"(d[3])
        : "r"(a[0]), "r"(a[1]), "r"(a[2]), "r"(a[3]), "r"(b[0]), "r"(b[1]));
}
#define LDSM4(r0, r1, r2, r3, addr) \
    asm volatile("ldmatrix.sync.aligned.m8n8.x4.shared.b16 {%0,%1,%2,%3}, [%4];" \
                 : "=r"(r0), "=r"(r1), "=r"(r2), "=r"(r3) : "r"(addr))
__device__ __forceinline__ unsigned packh2(float lo, float hi) {
    __half2 h = __floats2half2_rn(lo, hi);
    return *reinterpret_cast<unsigned*>(&h);
}
__device__ __forceinline__ void cp16(uint32_t d, const void* g) {
    asm volatile("cp.async.cg.shared.global [%0], [%1], 16;" :: "r"(d), "l"(g));
}
__device__ __forceinline__ void cp16g(uint32_t d, const void* g, int sz) {
    asm volatile("cp.async.cg.shared.global [%0], [%1], 16, %2;"
                 :: "r"(d), "l"(g), "r"(sz));
}

// ---------------- weight packing (once per replay) ----------------
__global__ void pack_t(const float* __restrict__ W, unsigned* __restrict__ out,
                       int K, int N)
{
    __shared__ float t[64][65];
    const int n0 = blockIdx.x * 64, k0 = blockIdx.y * 64, l = blockIdx.z;
    const float* Wl = W + (size_t)l * K * N;
    unsigned* ol = out + (size_t)l * N * (K >> 1);
    const int tid = threadIdx.x;
    #pragma unroll
    for (int p = 0; p < 16; p++) {
        int idx = tid + p * 256;
        int kk = idx >> 6, nn = idx & 63;
        t[kk][nn] = Wl[(size_t)(k0 + kk) * N + n0 + nn];
    }
    __syncthreads();
    #pragma unroll
    for (int p = 0; p < 8; p++) {
        int idx = tid + p * 256;
        int nn = idx >> 5, kp = idx & 31;
        ol[(size_t)(n0 + nn) * (K >> 1) + (k0 >> 1) + kp] =
            packh2(t[2 * kp][nn], t[2 * kp + 1][nn]);
    }
}
__global__ void pack_nk(const float* __restrict__ W, unsigned* __restrict__ out,
                        int total)
{
    int i = blockIdx.x * 256 + threadIdx.x;
    if (i >= total) return;
    int v = i / KPD, kp = i - v * KPD;
    float2 f = *(const float2*)(W + (size_t)v * DD + 2 * kp);
    out[i] = packh2(f.x, f.y);
}

// ---------------- V transpose: f32 [row][D] -> fp16 hi/lo [bh*64+dk][jpair] --
__global__ void vtrans_kernel(const float* __restrict__ v,
                              unsigned* __restrict__ vph,
                              unsigned* __restrict__ vpl)
{
    __shared__ float t[64][65];
    const int j0 = blockIdx.x * 64;
    const int bh = blockIdx.y;
    const int b = bh / HH, h = bh % HH;
    const int tid = threadIdx.x;
    #pragma unroll
    for (int p = 0; p < 16; p++) {
        int idx = tid + p * 256;
        int j = idx >> 6, dk = idx & 63;
        t[j][dk] = v[(size_t)(b * SS + j0 + j) * DD + h * DKK + dk];
    }
    __syncthreads();
    #pragma unroll
    for (int p = 0; p < 8; p++) {
        int idx = tid + p * 256;
        int dk = idx >> 5, jp = idx & 31;
        float v0 = t[2 * jp][dk], v1 = t[2 * jp + 1][dk];
        __half h0 = __float2half_rn(v0), h1 = __float2half_rn(v1);
        float l0 = v0 - __half2float(h0), l1 = v1 - __half2float(h1);
        __half2 hh = __halves2half2(h0, h1);
        size_t o = ((size_t)bh * DKK + dk) * (SS / 2) + (j0 >> 1) + jp;
        vph[o] = *reinterpret_cast<unsigned*>(&hh);
        vpl[o] = packh2(l0, l1);
    }
}

// ---------------- fp16 NT GEMM: 4 warps, 64x64 warp tiles, BK=64, 3-stage --
// EPI: 0 none->f32, 1 +Cin->f32, 2 GELU->packed fp16, 3 QKV (z<2 fp16, z=2 f32)
// NG: guard N (head gemm)
#define APAD 36
#define AW (128 * APAD)
#define STG (2 * AW)

template<int EPI, bool NG>
__global__ __launch_bounds__(128, 2)
void mma_gemm(const unsigned* __restrict__ A,
              const unsigned* __restrict__ B0, const unsigned* __restrict__ B1,
              const unsigned* __restrict__ B2,
              const float* __restrict__ Cin, void* __restrict__ Cv,
              float* __restrict__ C1f, float* __restrict__ C2f,
              int N, int K)
{
    extern __shared__ unsigned gsm[];

    const unsigned* B = (blockIdx.z == 0) ? B0 : ((blockIdx.z == 1) ? B1 : B2);
    float* Cf = (blockIdx.z == 0) ? (float*)Cv : ((blockIdx.z == 1) ? C1f : C2f);
    unsigned* C16 = (unsigned*)Cv;

    const int tid  = threadIdx.x;
    const int lane = tid & 31;
    const int warp = tid >> 5;                    // 0..3
    const int wm = warp >> 1, wn = warp & 1;      // 2 x 2, warp tile 64x64
    const int lr = lane >> 2, lq = lane & 3;
    const int m0 = blockIdx.y * 128;
    const int n0 = blockIdx.x * 128;
    const int KA = K >> 1;

    const uint32_t sbase = smem_u32(gsm);
    const int lrow = lane & 7, lg = lane >> 3;
    const uint32_t aoff = (uint32_t)(((wm * 64 + (lg & 1) * 8 + lrow) * APAD
                                      + (lg >> 1) * 4) * 4);
    const uint32_t boff = (uint32_t)(((wn * 64 + (lg >> 1) * 8 + lrow) * APAD
                                      + (lg & 1) * 4) * 4);

    float acc[4][8][4];
    #pragma unroll
    for (int i = 0; i < 4; i++)
        #pragma unroll
        for (int j = 0; j < 8; j++)
            #pragma unroll
            for (int t = 0; t < 4; t++) acc[i][j][t] = 0.0f;

    // per stage: 128 rows x 32 words per operand; 8 cp16/thread/operand
    auto load_stage = [&](int stg) {
        const int slot = stg % 3;
        const uint32_t sa = sbase + (uint32_t)(slot * STG) * 4u;
        const uint32_t sb = sa + (uint32_t)AW * 4u;
        const int kp0 = stg * 32;
        #pragma unroll
        for (int p = 0; p < 8; p++) {
            int s = tid + p * 128;                 // 0..1023
            int r = s >> 3, c4 = (s & 7) * 4;
            cp16(sa + (uint32_t)(r * APAD + c4) * 4u,
                 A + (size_t)(m0 + r) * KA + kp0 + c4);
        }
        #pragma unroll
        for (int p = 0; p < 8; p++) {
            int s = tid + p * 128;
            int r = s >> 3, c4 = (s & 7) * 4;
            if (NG) {
                int n = n0 + r;
                int ok = (n < N);
                cp16g(sb + (uint32_t)(r * APAD + c4) * 4u,
                      B + (size_t)(ok ? n : 0) * KA + kp0 + c4, ok ? 16 : 0);
            } else {
                cp16(sb + (uint32_t)(r * APAD + c4) * 4u,
                     B + (size_t)(n0 + r) * KA + kp0 + c4);
            }
        }
        asm volatile("cp.async.commit_group;" ::: "memory");
    };

    auto compute = [&](int slot) {
        const uint32_t sa = sbase + (uint32_t)(slot * STG) * 4u;
        const uint32_t sb = sa + (uint32_t)AW * 4u;
        #pragma unroll
        for (int kc = 0; kc < 4; kc++) {
            const uint32_t kbb = (uint32_t)(kc * 32);      // 8 words per K16
            unsigned af[4][4];
            #pragma unroll
            for (int mt = 0; mt < 4; mt++) {
                uint32_t addr = sa + aoff + kbb + (uint32_t)(mt * 16 * APAD * 4);
                LDSM4(af[mt][0], af[mt][1], af[mt][2], af[mt][3], addr);
            }
            unsigned bf[8][2];
            #pragma unroll
            for (int np = 0; np < 4; np++) {
                uint32_t addr = sb + boff + kbb + (uint32_t)(np * 16 * APAD * 4);
                unsigned r0, r1, r2, r3;
                LDSM4(r0, r1, r2, r3, addr);
                bf[np * 2][0] = r0;     bf[np * 2][1] = r1;
                bf[np * 2 + 1][0] = r2; bf[np * 2 + 1][1] = r3;
            }
            #pragma unroll
            for (int mt = 0; mt < 4; mt++)
                #pragma unroll
                for (int nt = 0; nt < 8; nt++)
                    mma16(acc[mt][nt], af[mt], bf[nt]);
        }
    };

    const int nIter = K >> 6;                      // BK = 64
    load_stage(0);
    load_stage(1);
    for (int it = 0; it < nIter; it++) {
        if (it + 1 < nIter) asm volatile("cp.async.wait_group 1;" ::: "memory");
        else                asm volatile("cp.async.wait_group 0;" ::: "memory");
        __syncthreads();
        if (it + 2 < nIter) load_stage(it + 2);
        compute(it % 3);
    }

    // ---- epilogue ----
    #pragma unroll
    for (int mt = 0; mt < 4; mt++) {
        int r0 = m0 + wm * 64 + mt * 16 + lr;
        #pragma unroll
        for (int nt = 0; nt < 8; nt++) {
            int col = n0 + wn * 64 + nt * 8 + lq * 2;
            float* a4 = acc[mt][nt];
            float v00 = a4[0], v01 = a4[1], v10 = a4[2], v11 = a4[3];
            if (EPI == 2) {
                v00 = 0.5f * v00 * (1.0f + erff(v00 * 0.70710678118654752f));
                v01 = 0.5f * v01 * (1.0f + erff(v01 * 0.70710678118654752f));
                v10 = 0.5f * v10 * (1.0f + erff(v10 * 0.70710678118654752f));
                v11 = 0.5f * v11 * (1.0f + erff(v11 * 0.70710678118654752f));
                int nw = N >> 1;
                C16[(size_t)r0 * nw + (col >> 1)]       = packh2(v00, v01);
                C16[(size_t)(r0 + 8) * nw + (col >> 1)] = packh2(v10, v11);
            } else if (EPI == 3) {
                if (blockIdx.z == 2) {
                    size_t o0 = (size_t)r0 * N + col;
                    size_t o1 = (size_t)(r0 + 8) * N + col;
                    *(float2*)(C2f + o0) = make_float2(v00, v01);
                    *(float2*)(C2f + o1) = make_float2(v10, v11);
                } else {
                    unsigned* o = (blockIdx.z == 0) ? (unsigned*)Cv : (unsigned*)C1f;
                    int nw = N >> 1;
                    o[(size_t)r0 * nw + (col >> 1)]       = packh2(v00, v01);
                    o[(size_t)(r0 + 8) * nw + (col >> 1)] = packh2(v10, v11);
                }
            } else {
                size_t o0 = (size_t)r0 * N + col;
                size_t o1 = (size_t)(r0 + 8) * N + col;
                if (EPI == 1) {
                    float2 c0 = *(const float2*)(Cin + o0);
                    float2 c1 = *(const float2*)(Cin + o1);
                    v00 += c0.x; v01 += c0.y; v10 += c1.x; v11 += c1.y;
                }
                if (!NG) {
                    *(float2*)(Cf + o0) = make_float2(v00, v01);
                    *(float2*)(Cf + o1) = make_float2(v10, v11);
                } else {
                    if (col < N)     { Cf[o0] = v00;     Cf[o1] = v10; }
                    if (col + 1 < N) { Cf[o0 + 1] = v01; Cf[o1 + 1] = v11; }
                }
            }
        }
    }
}

// ---------------- embedding ----------------
__global__ void embed_kernel(const int* __restrict__ idx,
                             const float* __restrict__ wte,
                             const float* __restrict__ wpe,
                             float* __restrict__ x)
{
    int row = blockIdx.x;
    int s   = row & (SS - 1);
    int tok = idx[row];
    int tid = threadIdx.x;
    #pragma unroll
    for (int l = 0; l < 3; l++) {
        int d = tid + l * 256;
        x[(size_t)row * DD + d] = wte[(size_t)tok * DD + d] + wpe[(size_t)s * DD + d];
    }
}

// ---------------- layernorm -> packed fp16 (shuffle reductions) ------------
__global__ void layernorm_kernel(const float* __restrict__ x,
                                 const float* __restrict__ w,
                                 const float* __restrict__ b,
                                 unsigned* __restrict__ y16)
{
    int row = blockIdx.x;
    const float2* p2 = (const float2*)(x + (size_t)row * DD);
    int tid = threadIdx.x;                 // 256
    int lane = tid & 31, wid = tid >> 5;
    float2 f1 = p2[tid];
    float2 f2 = (tid < 128) ? p2[tid + 256] : make_float2(0.f, 0.f);

    __shared__ float ws[8], ws2[8];
    float s = f1.x + f1.y + f2.x + f2.y;
    #pragma unroll
    for (int o = 16; o > 0; o >>= 1) s += __shfl_xor_sync(0xffffffffu, s, o);
    if (lane == 0) ws[wid] = s;
    __syncthreads();
    float mean = (ws[0] + ws[1] + ws[2] + ws[3] + ws[4] + ws[5] + ws[6] + ws[7])
                 * (1.0f / DD);

    float a0 = f1.x - mean, a1 = f1.y - mean;
    float a2 = f2.x - mean, a3 = f2.y - mean;
    float sq = a0 * a0 + a1 * a1 + ((tid < 128) ? (a2 * a2 + a3 * a3) : 0.f);
    #pragma unroll
    for (int o = 16; o > 0; o >>= 1) sq += __shfl_xor_sync(0xffffffffu, sq, o);
    if (lane == 0) ws2[wid] = sq;
    __syncthreads();
    float var = (ws2[0] + ws2[1] + ws2[2] + ws2[3] + ws2[4] + ws2[5] + ws2[6] + ws2[7])
                * (1.0f / DD);
    float rstd = rsqrtf(var + 1e-5f);

    const float2* w2 = (const float2*)w;
    const float2* b2 = (const float2*)b;
    unsigned* yr = y16 + (size_t)row * KPD;
    {
        float2 ww = w2[tid], bb = b2[tid];
        yr[tid] = packh2(a0 * rstd * ww.x + bb.x, a1 * rstd * ww.y + bb.y);
    }
    if (tid < 128) {
        float2 ww = w2[tid + 256], bb = b2[tid + 256];
        yr[tid + 256] = packh2(a2 * rstd * ww.x + bb.x, a3 * rstd * ww.y + bb.y);
    }
}

// ---------------- fused flash attention (fp16, double-buffered KV) ---------
#define FST 36   // smem row stride (32 words + 4 pad)
#define FQW (64 * FST)          // Q tile words
#define FBW (3 * 64 * FST)      // per-buffer words (K, Vh, Vl)
#define FA_SMEM_BYTES ((FQW + 2 * FBW) * 4)   // 64512

__global__ __launch_bounds__(128, 3)
void flash_attn_kernel(const unsigned* __restrict__ q16,
                       const unsigned* __restrict__ k16,
                       const unsigned* __restrict__ vph,
                       const unsigned* __restrict__ vpl,
                       unsigned* __restrict__ O16)
{
    extern __shared__ unsigned fsm[];

    const int tid  = threadIdx.x;
    const int lane = tid & 31;
    const int w    = tid >> 5;
    const int lr   = lane >> 2;
    const int lq   = lane & 3;
    const int it   = (SS / 64 - 1) - blockIdx.x;
    const int bh   = blockIdx.y;
    const int b    = bh / HH, h = bh % HH;
    const int i0   = it * 64;
    const int lrow = lane & 7, lg = lane >> 3;

    const uint32_t sQb = smem_u32(fsm);
    const uint32_t aoff = (uint32_t)(((w * 16 + (lg & 1) * 8 + lrow) * FST
                                      + (lg >> 1) * 4) * 4);
    const uint32_t boff = (uint32_t)((((lg >> 1) * 8 + lrow) * FST
                                      + (lg & 1) * 4) * 4);

    auto load_tile = [&](int j0, int buf) {
        const uint32_t kb  = sQb + (uint32_t)(FQW + buf * FBW) * 4u;
        const uint32_t vhb = kb + (uint32_t)(64 * FST) * 4u;
        const uint32_t vlb = vhb + (uint32_t)(64 * FST) * 4u;
        #pragma unroll
        for (int p = 0; p < 4; p++) {
            int s = tid + p * 128;
            int r = s >> 3, c4 = (s & 7) * 4;
            cp16(kb + (uint32_t)(r * FST + c4) * 4u,
                 k16 + (size_t)(b * SS + j0 + r) * KPD + h * 32 + c4);
            size_t vo = ((size_t)bh * DKK + r) * (SS / 2) + (j0 >> 1) + c4;
            cp16(vhb + (uint32_t)(r * FST + c4) * 4u, vph + vo);
            cp16(vlb + (uint32_t)(r * FST + c4) * 4u, vpl + vo);
        }
        asm volatile("cp.async.commit_group;" ::: "memory");
    };

    #pragma unroll
    for (int p = 0; p < 4; p++) {
        int s = tid + p * 128;
        int r = s >> 3, c4 = (s & 7) * 4;
        cp16(sQb + (uint32_t)(r * FST + c4) * 4u,
             q16 + (size_t)(b * SS + i0 + r) * KPD + h * 32 + c4);
    }
    asm volatile("cp.async.commit_group;" ::: "memory");
    load_tile(0, 0);
    asm volatile("cp.async.wait_group 1;" ::: "memory");
    __syncthreads();

    unsigned qf[4][4];
    #pragma unroll
    for (int kc = 0; kc < 4; kc++)
        LDSM4(qf[kc][0], qf[kc][1], qf[kc][2], qf[kc][3], sQb + aoff + kc * 32);

    float oacc[8][4];
    #pragma unroll
    for (int nt = 0; nt < 8; nt++)
        #pragma unroll
        for (int e = 0; e < 4; e++) oacc[nt][e] = 0.0f;
    float m0 = -1e30f, m1 = -1e30f, l0 = 0.0f, l1 = 0.0f;

    int buf = 0;
    for (int j0 = 0; j0 <= i0; j0 += 64) {
        __syncthreads();
        const bool more = (j0 + 64 <= i0);
        if (more) load_tile(j0 + 64, buf ^ 1);
        if (more) asm volatile("cp.async.wait_group 1;" ::: "memory");
        else      asm volatile("cp.async.wait_group 0;" ::: "memory");
        __syncthreads();

        const uint32_t kb  = sQb + (uint32_t)(FQW + buf * FBW) * 4u;
        const uint32_t vhb = kb + (uint32_t)(64 * FST) * 4u;
        const uint32_t vlb = vhb + (uint32_t)(64 * FST) * 4u;

        float sacc[8][4];
        #pragma unroll
        for (int nt = 0; nt < 8; nt++)
            #pragma unroll
            for (int e = 0; e < 4; e++) sacc[nt][e] = 0.0f;
        #pragma unroll
        for (int kc = 0; kc < 4; kc++) {
            #pragma unroll
            for (int nb = 0; nb < 4; nb++) {
                unsigned r0, r1, r2, r3;
                LDSM4(r0, r1, r2, r3,
                      kb + boff + (uint32_t)(nb * 16 * FST * 4) + kc * 32);
                unsigned b0[2] = {r0, r1}, b1[2] = {r2, r3};
                mma16(sacc[nb * 2],     qf[kc], b0);
                mma16(sacc[nb * 2 + 1], qf[kc], b1);
            }
        }

        #pragma unroll
        for (int nt = 0; nt < 8; nt++)
            #pragma unroll
            for (int e = 0; e < 4; e++) sacc[nt][e] *= 0.125f;
        if (j0 == i0) {
            int ii0 = w * 16 + lr, ii1 = ii0 + 8;
            #pragma unroll
            for (int nt = 0; nt < 8; nt++) {
                int jj = nt * 8 + 2 * lq;
                if (jj     > ii0) sacc[nt][0] = -1e30f;
                if (jj + 1 > ii0) sacc[nt][1] = -1e30f;
                if (jj     > ii1) sacc[nt][2] = -1e30f;
                if (jj + 1 > ii1) sacc[nt][3] = -1e30f;
            }
        }

        float rm0 = -1e30f, rm1 = -1e30f;
        #pragma unroll
        for (int nt = 0; nt < 8; nt++) {
            rm0 = fmaxf(rm0, fmaxf(sacc[nt][0], sacc[nt][1]));
            rm1 = fmaxf(rm1, fmaxf(sacc[nt][2], sacc[nt][3]));
        }
        rm0 = fmaxf(rm0, __shfl_xor_sync(0xffffffffu, rm0, 1));
        rm0 = fmaxf(rm0, __shfl_xor_sync(0xffffffffu, rm0, 2));
        rm1 = fmaxf(rm1, __shfl_xor_sync(0xffffffffu, rm1, 1));
        rm1 = fmaxf(rm1, __shfl_xor_sync(0xffffffffu, rm1, 2));
        float mn0 = fmaxf(m0, rm0), mn1 = fmaxf(m1, rm1);
        float f0 = __expf(m0 - mn0), f1 = __expf(m1 - mn1);
        float ps0 = 0.0f, ps1 = 0.0f;
        #pragma unroll
        for (int nt = 0; nt < 8; nt++) {
            float p0 = __expf(sacc[nt][0] - mn0); sacc[nt][0] = p0; ps0 += p0;
            float p1 = __expf(sacc[nt][1] - mn0); sacc[nt][1] = p1; ps0 += p1;
            float p2 = __expf(sacc[nt][2] - mn1); sacc[nt][2] = p2; ps1 += p2;
            float p3 = __expf(sacc[nt][3] - mn1); sacc[nt][3] = p3; ps1 += p3;
        }
        ps0 += __shfl_xor_sync(0xffffffffu, ps0, 1);
        ps0 += __shfl_xor_sync(0xffffffffu, ps0, 2);
        ps1 += __shfl_xor_sync(0xffffffffu, ps1, 1);
        ps1 += __shfl_xor_sync(0xffffffffu, ps1, 2);
        l0 = l0 * f0 + ps0;
        l1 = l1 * f1 + ps1;
        m0 = mn0; m1 = mn1;
        #pragma unroll
        for (int nt = 0; nt < 8; nt++) {
            oacc[nt][0] *= f0; oacc[nt][1] *= f0;
            oacc[nt][2] *= f1; oacc[nt][3] *= f1;
        }

        #pragma unroll
        for (int kc = 0; kc < 4; kc++) {
            unsigned ah[4], al[4];
            #pragma unroll
            for (int hsel = 0; hsel < 2; hsel++) {
                const float* s0 = sacc[2 * kc + hsel];
                unsigned hi0 = packh2(s0[0], s0[1]);
                unsigned hi1 = packh2(s0[2], s0[3]);
                __half2 h2a = *reinterpret_cast<__half2*>(&hi0);
                __half2 h2b = *reinterpret_cast<__half2*>(&hi1);
                float2 fa = __half22float2(h2a);
                float2 fb = __half22float2(h2b);
                ah[hsel * 2]     = hi0;
                ah[hsel * 2 + 1] = hi1;
                al[hsel * 2]     = packh2(s0[0] - fa.x, s0[1] - fa.y);
                al[hsel * 2 + 1] = packh2(s0[2] - fb.x, s0[3] - fb.y);
            }
            #pragma unroll
            for (int nb = 0; nb < 4; nb++) {
                uint32_t va = boff + (uint32_t)(nb * 16 * FST * 4) + kc * 32;
                unsigned h0, h1, h2, h3, g0, g1, g2, g3;
                LDSM4(h0, h1, h2, h3, vhb + va);
                LDSM4(g0, g1, g2, g3, vlb + va);
                unsigned bh0[2] = {h0, h1}, bh1[2] = {h2, h3};
                unsigned bl0[2] = {g0, g1}, bl1[2] = {g2, g3};
                mma16(oacc[nb * 2],     ah, bh0);
                mma16(oacc[nb * 2],     al, bh0);
                mma16(oacc[nb * 2],     ah, bl0);
                mma16(oacc[nb * 2 + 1], ah, bh1);
                mma16(oacc[nb * 2 + 1], al, bh1);
                mma16(oacc[nb * 2 + 1], ah, bl1);
            }
        }
        buf ^= 1;
    }

    float inv0 = 1.0f / l0, inv1 = 1.0f / l1;
    int row0 = b * SS + i0 + w * 16 + lr;
    unsigned* Ob = O16 + (size_t)row0 * KPD + h * 32;
    #pragma unroll
    for (int nt = 0; nt < 8; nt++) {
        Ob[nt * 4 + lq] = packh2(oacc[nt][0] * inv0, oacc[nt][1] * inv0);
        Ob[(size_t)8 * KPD + nt * 4 + lq] = packh2(oacc[nt][2] * inv1, oacc[nt][3] * inv1);
    }
}

// ---------------- host launcher ----------------
extern "C" void kernel_launch(void* const* d_in, const int* in_sizes, int n_in,
                              void* d_out, int out_size)
{
    const int*   idx   = (const int*)  d_in[0];
    const float* wte   = (const float*)d_in[1];
    const float* wpe   = (const float*)d_in[2];
    const float* ln1_w = (const float*)d_in[3];
    const float* ln1_b = (const float*)d_in[4];
    const float* wq    = (const float*)d_in[5];
    const float* wk    = (const float*)d_in[6];
    const float* wv    = (const float*)d_in[7];
    const float* wo    = (const float*)d_in[8];
    const float* ln2_w = (const float*)d_in[9];
    const float* ln2_b = (const float*)d_in[10];
    const float* fc1   = (const float*)d_in[11];
    const float* fc2   = (const float*)d_in[12];
    const float* lnf_w = (const float*)d_in[13];
    const float* lnf_b = (const float*)d_in[14];
    float* out = (float*)d_out;

    float *x, *v;
    unsigned *q16, *k16, *h16, *tmp16, *ff16, *vph, *vpl;
    unsigned *wq16, *wk16, *wv16, *wo16, *fc116, *fc216, *wte16;
    cudaGetSymbolAddress((void**)&x,     g_x);
    cudaGetSymbolAddress((void**)&v,     g_v);
    cudaGetSymbolAddress((void**)&q16,   g_q16);
    cudaGetSymbolAddress((void**)&k16,   g_k16);
    cudaGetSymbolAddress((void**)&h16,   g_h16);
    cudaGetSymbolAddress((void**)&tmp16, g_tmp16);
    cudaGetSymbolAddress((void**)&ff16,  g_ff16);
    cudaGetSymbolAddress((void**)&vph,   g_vph);
    cudaGetSymbolAddress((void**)&vpl,   g_vpl);
    cudaGetSymbolAddress((void**)&wq16,  g_wq16);
    cudaGetSymbolAddress((void**)&wk16,  g_wk16);
    cudaGetSymbolAddress((void**)&wv16,  g_wv16);
    cudaGetSymbolAddress((void**)&wo16,  g_wo16);
    cudaGetSymbolAddress((void**)&fc116, g_fc116);
    cudaGetSymbolAddress((void**)&fc216, g_fc216);
    cudaGetSymbolAddress((void**)&wte16, g_wte16);

    const int gs = 3 * STG * 4;      // 110592 bytes
    cudaFuncSetAttribute(mma_gemm<0,false>, cudaFuncAttributeMaxDynamicSharedMemorySize, gs);
    cudaFuncSetAttribute(mma_gemm<1,false>, cudaFuncAttributeMaxDynamicSharedMemorySize, gs);
    cudaFuncSetAttribute(mma_gemm<2,false>, cudaFuncAttributeMaxDynamicSharedMemorySize, gs);
    cudaFuncSetAttribute(mma_gemm<3,false>, cudaFuncAttributeMaxDynamicSharedMemorySize, gs);
    cudaFuncSetAttribute(mma_gemm<0,true>,  cudaFuncAttributeMaxDynamicSharedMemorySize, gs);
    cudaFuncSetAttribute(flash_attn_kernel,
                         cudaFuncAttributeMaxDynamicSharedMemorySize, FA_SMEM_BYTES);

    pack_t<<<dim3(DD / 64, DD / 64, LL), 256>>>(wq, wq16, DD, DD);
    pack_t<<<dim3(DD / 64, DD / 64, LL), 256>>>(wk, wk16, DD, DD);
    pack_t<<<dim3(DD / 64, DD / 64, LL), 256>>>(wv, wv16, DD, DD);
    pack_t<<<dim3(DD / 64, DD / 64, LL), 256>>>(wo, wo16, DD, DD);
    pack_t<<<dim3(DFF / 64, DD / 64, LL), 256>>>(fc1, fc116, DD, DFF);
    pack_t<<<dim3(DD / 64, DFF / 64, LL), 256>>>(fc2, fc216, DFF, DD);
    {
        int tE = VV * KPD;
        pack_nk<<<(tE + 255) / 256, 256>>>(wte, wte16, tE);
    }

    embed_kernel<<<NTOK, 256>>>(idx, wte, wpe, x);

    dim3 gQKV(DD / 128, NTOK / 128, 3);
    dim3 gD  (DD / 128, NTOK / 128, 1);
    dim3 gF  (DFF / 128, NTOK / 128, 1);

    for (int l = 0; l < LL; l++) {
        unsigned* Wq = wq16 + (size_t)l * DD * KPD;
        unsigned* Wk = wk16 + (size_t)l * DD * KPD;
        unsigned* Wv = wv16 + (size_t)l * DD * KPD;
        unsigned* Wo = wo16 + (size_t)l * DD * KPD;
        unsigned* W1 = fc116 + (size_t)l * DFF * KPD;
        unsigned* W2 = fc216 + (size_t)l * DD * KPF;

        layernorm_kernel<<<NTOK, 256>>>(x, ln1_w + l * DD, ln1_b + l * DD, h16);

        mma_gemm<3,false><<<gQKV, 128, gs>>>(h16, Wq, Wk, Wv, nullptr,
                                             q16, (float*)k16, v, DD, DD);

        vtrans_kernel<<<dim3(SS / 64, BB * HH), 256>>>(v, vph, vpl);

        flash_attn_kernel<<<dim3(SS / 64, BB * HH), 128, FA_SMEM_BYTES>>>(
            q16, k16, vph, vpl, tmp16);

        mma_gemm<1,false><<<gD, 128, gs>>>(tmp16, Wo, Wo, Wo, x, x,
                                           nullptr, nullptr, DD, DD);

        layernorm_kernel<<<NTOK, 256>>>(x, ln2_w + l * DD, ln2_b + l * DD, h16);
        mma_gemm<2,false><<<gF, 128, gs>>>(h16, W1, W1, W1, nullptr, ff16,
                                           nullptr, nullptr, DFF, DD);
        mma_gemm<1,false><<<gD, 128, gs>>>(ff16, W2, W2, W2, x, x,
                                           nullptr, nullptr, DD, DFF);
    }

    layernorm_kernel<<<NTOK, 256>>>(x, lnf_w, lnf_b, h16);
    mma_gemm<0,true><<<dim3((VV + 127) / 128, NTOK / 128, 1), 128, gs>>>(
        h16, wte16, wte16, wte16, nullptr, out, nullptr, nullptr, VV, DD);
}

// round 14
// speedup vs baseline: 1.0418x; 1.0418x over previous
#include <cuda_runtime.h>
#include <cuda_bf16.h>
#include <cuda_fp16.h>
#include <math.h>
#include <stdint.h>

// ---------------- problem constants ----------------
#define BB 4
#define SS 1024
#define LL 12
#define DD 768
#define HH 12
#define DKK 64
#define DFF 3072
#define VV 50257
#define NTOK (BB*SS)          // 4096
#define KPD (DD/2)            // 384
#define KPF (DFF/2)           // 1536

// ---------------- scratch (device globals; no allocs allowed) --------------
__device__ unsigned g_q16 [(size_t)NTOK * KPD];
__device__ unsigned g_k16 [(size_t)NTOK * KPD];
__device__ unsigned g_h16 [(size_t)NTOK * KPD];
__device__ unsigned g_tmp16[(size_t)NTOK * KPD];
__device__ unsigned g_ff16 [(size_t)NTOK * KPF];
__device__ float    g_x   [(size_t)NTOK * DD];
__device__ unsigned g_vph [(size_t)BB * HH * DKK * (SS/2)];
__device__ unsigned g_vpl [(size_t)BB * HH * DKK * (SS/2)];
// packed fp16 weights, K-major: [L][N][K/2] half2 words
__device__ unsigned g_wq16 [(size_t)LL * DD * KPD];
__device__ unsigned g_wk16 [(size_t)LL * DD * KPD];
__device__ unsigned g_wv16 [(size_t)LL * DD * KPD];
__device__ unsigned g_wo16 [(size_t)LL * DD * KPD];
__device__ unsigned g_fc116[(size_t)LL * DFF * KPD];
__device__ unsigned g_fc216[(size_t)LL * DD * KPF];
__device__ unsigned g_wte16[(size_t)VV * KPD];

// ---------------- helpers ----------------
__device__ __forceinline__ uint32_t smem_u32(const void* p) {
    uint32_t a;
    asm("{ .reg .u64 t; cvta.to.shared.u64 t, %1; cvt.u32.u64 %0, t; }"
        : "=r"(a) : "l"(p));
    return a;
}
__device__ __forceinline__ void mma16(float* d, const unsigned* a, const unsigned* b) {
    asm volatile(
        "mma.sync.aligned.m16n8k16.row.col.f32.f16.f16.f32 "
        "{%0,%1,%2,%3},{%4,%5,%6,%7},{%8,%9},{%0,%1,%2,%3};"
        : "+f"(d[0]), "+f"(d[1]), "+f"(d[2]), "+f"(d[3])
        : "r"(a[0]), "r"(a[1]), "r"(a[2]), "r"(a[3]), "r"(b[0]), "r"(b[1]));
}
#define LDSM4(r0, r1, r2, r3, addr) \
    asm volatile("ldmatrix.sync.aligned.m8n8.x4.shared.b16 {%0,%1,%2,%3}, [%4];" \
                 : "=r"(r0), "=r"(r1), "=r"(r2), "=r"(r3) : "r"(addr))
__device__ __forceinline__ unsigned packh2(float lo, float hi) {
    __half2 h = __floats2half2_rn(lo, hi);
    return *reinterpret_cast<unsigned*>(&h);
}
__device__ __forceinline__ void cp16(uint32_t d, const void* g) {
    asm volatile("cp.async.cg.shared.global [%0], [%1], 16;" :: "r"(d), "l"(g));
}
__device__ __forceinline__ void cp16g(uint32_t d, const void* g, int sz) {
    asm volatile("cp.async.cg.shared.global [%0], [%1], 16, %2;"
                 :: "r"(d), "l"(g), "r"(sz));
}

// ---------------- weight packing (once per replay) ----------------
__global__ void pack_t(const float* __restrict__ W, unsigned* __restrict__ out,
                       int K, int N)
{
    __shared__ float t[64][65];
    const int n0 = blockIdx.x * 64, k0 = blockIdx.y * 64, l = blockIdx.z;
    const float* Wl = W + (size_t)l * K * N;
    unsigned* ol = out + (size_t)l * N * (K >> 1);
    const int tid = threadIdx.x;
    #pragma unroll
    for (int p = 0; p < 16; p++) {
        int idx = tid + p * 256;
        int kk = idx >> 6, nn = idx & 63;
        t[kk][nn] = Wl[(size_t)(k0 + kk) * N + n0 + nn];
    }
    __syncthreads();
    #pragma unroll
    for (int p = 0; p < 8; p++) {
        int idx = tid + p * 256;
        int nn = idx >> 5, kp = idx & 31;
        ol[(size_t)(n0 + nn) * (K >> 1) + (k0 >> 1) + kp] =
            packh2(t[2 * kp][nn], t[2 * kp + 1][nn]);
    }
}
__global__ void pack_nk(const float* __restrict__ W, unsigned* __restrict__ out,
                        int total)
{
    int i = blockIdx.x * 256 + threadIdx.x;
    if (i >= total) return;
    int v = i / KPD, kp = i - v * KPD;
    float2 f = *(const float2*)(W + (size_t)v * DD + 2 * kp);
    out[i] = packh2(f.x, f.y);
}

// ---------------- fp16 NT GEMM: 8 warps, BK=64, 3-stage (R11 config) -------
// EPI: 0 none->f32, 1 +Cin->f32, 2 GELU->packed fp16,
//      3 QKV: z0->q16, z1->k16, z2->fused V transpose to vph/vpl
// NG: guard N (head gemm; N odd -> scalar stores only)
#define APAD 36
#define AW (128 * APAD)
#define STG (2 * AW)

template<int EPI, bool NG>
__global__ __launch_bounds__(256, 2)
void mma_gemm(const unsigned* __restrict__ A,
              const unsigned* __restrict__ B0, const unsigned* __restrict__ B1,
              const unsigned* __restrict__ B2,
              const float* __restrict__ Cin, void* __restrict__ Cv,
              float* __restrict__ C1f,
              unsigned* __restrict__ Vh, unsigned* __restrict__ Vl,
              int N, int K)
{
    extern __shared__ unsigned gsm[];

    const unsigned* B = (blockIdx.z == 0) ? B0 : ((blockIdx.z == 1) ? B1 : B2);
    float* Cf = (blockIdx.z == 0) ? (float*)Cv : C1f;
    unsigned* C16 = (unsigned*)Cv;

    const int tid  = threadIdx.x;
    const int lane = tid & 31;
    const int warp = tid >> 5;
    const int wm = warp >> 2, wn = warp & 3;       // 2 x 4, warp tile 64x32
    const int lr = lane >> 2, lq = lane & 3;
    const int m0 = blockIdx.y * 128;
    const int n0 = blockIdx.x * 128;
    const int KA = K >> 1;

    const uint32_t sbase = smem_u32(gsm);
    const int lrow = lane & 7, lg = lane >> 3;
    const uint32_t aoff = (uint32_t)(((wm * 64 + (lg & 1) * 8 + lrow) * APAD
                                      + (lg >> 1) * 4) * 4);
    const uint32_t boff = (uint32_t)(((wn * 32 + (lg >> 1) * 8 + lrow) * APAD
                                      + (lg & 1) * 4) * 4);

    float acc[4][4][4];
    #pragma unroll
    for (int i = 0; i < 4; i++)
        #pragma unroll
        for (int j = 0; j < 4; j++)
            #pragma unroll
            for (int t = 0; t < 4; t++) acc[i][j][t] = 0.0f;

    auto load_stage = [&](int stg) {
        const int slot = stg % 3;
        const uint32_t sa = sbase + (uint32_t)(slot * STG) * 4u;
        const uint32_t sb = sa + (uint32_t)AW * 4u;
        const int kp0 = stg * 32;
        #pragma unroll
        for (int p = 0; p < 4; p++) {
            int s = tid + p * 256;
            int r = s >> 3, c4 = (s & 7) * 4;
            cp16(sa + (uint32_t)(r * APAD + c4) * 4u,
                 A + (size_t)(m0 + r) * KA + kp0 + c4);
        }
        #pragma unroll
        for (int p = 0; p < 4; p++) {
            int s = tid + p * 256;
            int r = s >> 3, c4 = (s & 7) * 4;
            if (NG) {
                int n = n0 + r;
                int ok = (n < N);
                cp16g(sb + (uint32_t)(r * APAD + c4) * 4u,
                      B + (size_t)(ok ? n : 0) * KA + kp0 + c4, ok ? 16 : 0);
            } else {
                cp16(sb + (uint32_t)(r * APAD + c4) * 4u,
                     B + (size_t)(n0 + r) * KA + kp0 + c4);
            }
        }
        asm volatile("cp.async.commit_group;" ::: "memory");
    };

    auto compute = [&](int slot) {
        const uint32_t sa = sbase + (uint32_t)(slot * STG) * 4u;
        const uint32_t sb = sa + (uint32_t)AW * 4u;
        #pragma unroll
        for (int kc = 0; kc < 4; kc++) {
            const uint32_t kbb = (uint32_t)(kc * 32);
            unsigned af[4][4];
            #pragma unroll
            for (int mt = 0; mt < 4; mt++) {
                uint32_t addr = sa + aoff + kbb + (uint32_t)(mt * 16 * APAD * 4);
                LDSM4(af[mt][0], af[mt][1], af[mt][2], af[mt][3], addr);
            }
            unsigned bf[4][2];
            #pragma unroll
            for (int np = 0; np < 2; np++) {
                uint32_t addr = sb + boff + kbb + (uint32_t)(np * 16 * APAD * 4);
                unsigned r0, r1, r2, r3;
                LDSM4(r0, r1, r2, r3, addr);
                bf[np * 2][0] = r0;     bf[np * 2][1] = r1;
                bf[np * 2 + 1][0] = r2; bf[np * 2 + 1][1] = r3;
            }
            #pragma unroll
            for (int mt = 0; mt < 4; mt++)
                #pragma unroll
                for (int nt = 0; nt < 4; nt++)
                    mma16(acc[mt][nt], af[mt], bf[nt]);
        }
    };

    const int nIter = K >> 6;
    load_stage(0);
    load_stage(1);
    for (int it = 0; it < nIter; it++) {
        if (it + 1 < nIter) asm volatile("cp.async.wait_group 1;" ::: "memory");
        else                asm volatile("cp.async.wait_group 0;" ::: "memory");
        __syncthreads();
        if (it + 2 < nIter) load_stage(it + 2);
        compute(it % 3);
    }

    // ---- fused V transpose epilogue (EPI==3, z==2) ----
    if (EPI == 3 && blockIdx.z == 2) {
        float* st = (float*)gsm;               // [128][129] f32 (66 KB)
        __syncthreads();                       // all warps done with stage smem
        #pragma unroll
        for (int mt = 0; mt < 4; mt++) {
            int r = wm * 64 + mt * 16 + lr;
            #pragma unroll
            for (int nt = 0; nt < 4; nt++) {
                int c = wn * 32 + nt * 8 + lq * 2;
                float* a4 = acc[mt][nt];
                st[r * 129 + c]           = a4[0];
                st[r * 129 + c + 1]       = a4[1];
                st[(r + 8) * 129 + c]     = a4[2];
                st[(r + 8) * 129 + c + 1] = a4[3];
            }
        }
        __syncthreads();
        const int b  = m0 / SS;
        const int j0 = m0 & (SS - 1);
        #pragma unroll
        for (int p = 0; p < 32; p++) {
            int idx = tid + p * 256;           // 0..8191
            int cc = idx >> 6, jp = idx & 63;
            float v0 = st[(2 * jp) * 129 + cc];
            float v1 = st[(2 * jp + 1) * 129 + cc];
            unsigned hi = packh2(v0, v1);
            __half2 hh = *reinterpret_cast<__half2*>(&hi);
            float2 fh = __half22float2(hh);
            unsigned lo = packh2(v0 - fh.x, v1 - fh.y);
            int h  = (n0 + cc) >> 6;
            int dk = (n0 + cc) & 63;
            size_t o = ((size_t)(b * HH + h) * DKK + dk) * (SS / 2) + (j0 >> 1) + jp;
            Vh[o] = hi;
            Vl[o] = lo;
        }
        return;
    }

    // ---- standard epilogues ----
    #pragma unroll
    for (int mt = 0; mt < 4; mt++) {
        int r0 = m0 + wm * 64 + mt * 16 + lr;
        #pragma unroll
        for (int nt = 0; nt < 4; nt++) {
            int col = n0 + wn * 32 + nt * 8 + lq * 2;
            float* a4 = acc[mt][nt];
            float v00 = a4[0], v01 = a4[1], v10 = a4[2], v11 = a4[3];
            if (EPI == 2) {
                v00 = 0.5f * v00 * (1.0f + erff(v00 * 0.70710678118654752f));
                v01 = 0.5f * v01 * (1.0f + erff(v01 * 0.70710678118654752f));
                v10 = 0.5f * v10 * (1.0f + erff(v10 * 0.70710678118654752f));
                v11 = 0.5f * v11 * (1.0f + erff(v11 * 0.70710678118654752f));
                int nw = N >> 1;
                C16[(size_t)r0 * nw + (col >> 1)]       = packh2(v00, v01);
                C16[(size_t)(r0 + 8) * nw + (col >> 1)] = packh2(v10, v11);
            } else if (EPI == 3) {
                unsigned* o = (blockIdx.z == 0) ? (unsigned*)Cv : (unsigned*)C1f;
                int nw = N >> 1;
                o[(size_t)r0 * nw + (col >> 1)]       = packh2(v00, v01);
                o[(size_t)(r0 + 8) * nw + (col >> 1)] = packh2(v10, v11);
            } else {
                size_t o0 = (size_t)r0 * N + col;
                size_t o1 = (size_t)(r0 + 8) * N + col;
                if (EPI == 1) {
                    float2 c0 = *(const float2*)(Cin + o0);
                    float2 c1 = *(const float2*)(Cin + o1);
                    v00 += c0.x; v01 += c0.y; v10 += c1.x; v11 += c1.y;
                }
                if (!NG) {
                    *(float2*)(Cf + o0) = make_float2(v00, v01);
                    *(float2*)(Cf + o1) = make_float2(v10, v11);
                } else {
                    // N odd (head gemm): scalar stores only — float2 at
                    // r0*N+col can be 4B-aligned when r0*N is odd.
                    if (col < N)     { Cf[o0] = v00;     Cf[o1] = v10; }
                    if (col + 1 < N) { Cf[o0 + 1] = v01; Cf[o1 + 1] = v11; }
                }
            }
        }
    }
}

// ---------------- embedding ----------------
__global__ void embed_kernel(const int* __restrict__ idx,
                             const float* __restrict__ wte,
                             const float* __restrict__ wpe,
                             float* __restrict__ x)
{
    int row = blockIdx.x;
    int s   = row & (SS - 1);
    int tok = idx[row];
    int tid = threadIdx.x;
    #pragma unroll
    for (int l = 0; l < 3; l++) {
        int d = tid + l * 256;
        x[(size_t)row * DD + d] = wte[(size_t)tok * DD + d] + wpe[(size_t)s * DD + d];
    }
}

// ---------------- layernorm -> packed fp16 (shuffle reductions) ------------
__global__ void layernorm_kernel(const float* __restrict__ x,
                                 const float* __restrict__ w,
                                 const float* __restrict__ b,
                                 unsigned* __restrict__ y16)
{
    int row = blockIdx.x;
    const float2* p2 = (const float2*)(x + (size_t)row * DD);
    int tid = threadIdx.x;                 // 256
    int lane = tid & 31, wid = tid >> 5;
    float2 f1 = p2[tid];
    float2 f2 = (tid < 128) ? p2[tid + 256] : make_float2(0.f, 0.f);

    __shared__ float ws[8], ws2[8];
    float s = f1.x + f1.y + f2.x + f2.y;
    #pragma unroll
    for (int o = 16; o > 0; o >>= 1) s += __shfl_xor_sync(0xffffffffu, s, o);
    if (lane == 0) ws[wid] = s;
    __syncthreads();
    float mean = (ws[0] + ws[1] + ws[2] + ws[3] + ws[4] + ws[5] + ws[6] + ws[7])
                 * (1.0f / DD);

    float a0 = f1.x - mean, a1 = f1.y - mean;
    float a2 = f2.x - mean, a3 = f2.y - mean;
    float sq = a0 * a0 + a1 * a1 + ((tid < 128) ? (a2 * a2 + a3 * a3) : 0.f);
    #pragma unroll
    for (int o = 16; o > 0; o >>= 1) sq += __shfl_xor_sync(0xffffffffu, sq, o);
    if (lane == 0) ws2[wid] = sq;
    __syncthreads();
    float var = (ws2[0] + ws2[1] + ws2[2] + ws2[3] + ws2[4] + ws2[5] + ws2[6] + ws2[7])
                * (1.0f / DD);
    float rstd = rsqrtf(var + 1e-5f);

    const float2* w2 = (const float2*)w;
    const float2* b2 = (const float2*)b;
    unsigned* yr = y16 + (size_t)row * KPD;
    {
        float2 ww = w2[tid], bb = b2[tid];
        yr[tid] = packh2(a0 * rstd * ww.x + bb.x, a1 * rstd * ww.y + bb.y);
    }
    if (tid < 128) {
        float2 ww = w2[tid + 256], bb = b2[tid + 256];
        yr[tid + 256] = packh2(a2 * rstd * ww.x + bb.x, a3 * rstd * ww.y + bb.y);
    }
}

// ---------------- fused flash attention (fp16, double-buffered KV) ---------
#define FST 36
#define FQW (64 * FST)
#define FBW (3 * 64 * FST)
#define FA_SMEM_BYTES ((FQW + 2 * FBW) * 4)   // 64512

__global__ __launch_bounds__(128, 3)
void flash_attn_kernel(const unsigned* __restrict__ q16,
                       const unsigned* __restrict__ k16,
                       const unsigned* __restrict__ vph,
                       const unsigned* __restrict__ vpl,
                       unsigned* __restrict__ O16)
{
    extern __shared__ unsigned fsm[];

    const int tid  = threadIdx.x;
    const int lane = tid & 31;
    const int w    = tid >> 5;
    const int lr   = lane >> 2;
    const int lq   = lane & 3;
    const int it   = (SS / 64 - 1) - blockIdx.x;
    const int bh   = blockIdx.y;
    const int b    = bh / HH, h = bh % HH;
    const int i0   = it * 64;
    const int lrow = lane & 7, lg = lane >> 3;

    const uint32_t sQb = smem_u32(fsm);
    const uint32_t aoff = (uint32_t)(((w * 16 + (lg & 1) * 8 + lrow) * FST
                                      + (lg >> 1) * 4) * 4);
    const uint32_t boff = (uint32_t)((((lg >> 1) * 8 + lrow) * FST
                                      + (lg & 1) * 4) * 4);

    auto load_tile = [&](int j0, int buf) {
        const uint32_t kb  = sQb + (uint32_t)(FQW + buf * FBW) * 4u;
        const uint32_t vhb = kb + (uint32_t)(64 * FST) * 4u;
        const uint32_t vlb = vhb + (uint32_t)(64 * FST) * 4u;
        #pragma unroll
        for (int p = 0; p < 4; p++) {
            int s = tid + p * 128;
            int r = s >> 3, c4 = (s & 7) * 4;
            cp16(kb + (uint32_t)(r * FST + c4) * 4u,
                 k16 + (size_t)(b * SS + j0 + r) * KPD + h * 32 + c4);
            size_t vo = ((size_t)bh * DKK + r) * (SS / 2) + (j0 >> 1) + c4;
            cp16(vhb + (uint32_t)(r * FST + c4) * 4u, vph + vo);
            cp16(vlb + (uint32_t)(r * FST + c4) * 4u, vpl + vo);
        }
        asm volatile("cp.async.commit_group;" ::: "memory");
    };

    #pragma unroll
    for (int p = 0; p < 4; p++) {
        int s = tid + p * 128;
        int r = s >> 3, c4 = (s & 7) * 4;
        cp16(sQb + (uint32_t)(r * FST + c4) * 4u,
             q16 + (size_t)(b * SS + i0 + r) * KPD + h * 32 + c4);
    }
    asm volatile("cp.async.commit_group;" ::: "memory");
    load_tile(0, 0);
    asm volatile("cp.async.wait_group 1;" ::: "memory");
    __syncthreads();

    unsigned qf[4][4];
    #pragma unroll
    for (int kc = 0; kc < 4; kc++)
        LDSM4(qf[kc][0], qf[kc][1], qf[kc][2], qf[kc][3], sQb + aoff + kc * 32);

    float oacc[8][4];
    #pragma unroll
    for (int nt = 0; nt < 8; nt++)
        #pragma unroll
        for (int e = 0; e < 4; e++) oacc[nt][e] = 0.0f;
    float m0 = -1e30f, m1 = -1e30f, l0 = 0.0f, l1 = 0.0f;

    int buf = 0;
    for (int j0 = 0; j0 <= i0; j0 += 64) {
        __syncthreads();
        const bool more = (j0 + 64 <= i0);
        if (more) load_tile(j0 + 64, buf ^ 1);
        if (more) asm volatile("cp.async.wait_group 1;" ::: "memory");
        else      asm volatile("cp.async.wait_group 0;" ::: "memory");
        __syncthreads();

        const uint32_t kb  = sQb + (uint32_t)(FQW + buf * FBW) * 4u;
        const uint32_t vhb = kb + (uint32_t)(64 * FST) * 4u;
        const uint32_t vlb = vhb + (uint32_t)(64 * FST) * 4u;

        float sacc[8][4];
        #pragma unroll
        for (int nt = 0; nt < 8; nt++)
            #pragma unroll
            for (int e = 0; e < 4; e++) sacc[nt][e] = 0.0f;
        #pragma unroll
        for (int kc = 0; kc < 4; kc++) {
            #pragma unroll
            for (int nb = 0; nb < 4; nb++) {
                unsigned r0, r1, r2, r3;
                LDSM4(r0, r1, r2, r3,
                      kb + boff + (uint32_t)(nb * 16 * FST * 4) + kc * 32);
                unsigned b0[2] = {r0, r1}, b1[2] = {r2, r3};
                mma16(sacc[nb * 2],     qf[kc], b0);
                mma16(sacc[nb * 2 + 1], qf[kc], b1);
            }
        }

        #pragma unroll
        for (int nt = 0; nt < 8; nt++)
            #pragma unroll
            for (int e = 0; e < 4; e++) sacc[nt][e] *= 0.125f;
        if (j0 == i0) {
            int ii0 = w * 16 + lr, ii1 = ii0 + 8;
            #pragma unroll
            for (int nt = 0; nt < 8; nt++) {
                int jj = nt * 8 + 2 * lq;
                if (jj     > ii0) sacc[nt][0] = -1e30f;
                if (jj + 1 > ii0) sacc[nt][1] = -1e30f;
                if (jj     > ii1) sacc[nt][2] = -1e30f;
                if (jj + 1 > ii1) sacc[nt][3] = -1e30f;
            }
        }

        float rm0 = -1e30f, rm1 = -1e30f;
        #pragma unroll
        for (int nt = 0; nt < 8; nt++) {
            rm0 = fmaxf(rm0, fmaxf(sacc[nt][0], sacc[nt][1]));
            rm1 = fmaxf(rm1, fmaxf(sacc[nt][2], sacc[nt][3]));
        }
        rm0 = fmaxf(rm0, __shfl_xor_sync(0xffffffffu, rm0, 1));
        rm0 = fmaxf(rm0, __shfl_xor_sync(0xffffffffu, rm0, 2));
        rm1 = fmaxf(rm1, __shfl_xor_sync(0xffffffffu, rm1, 1));
        rm1 = fmaxf(rm1, __shfl_xor_sync(0xffffffffu, rm1, 2));
        float mn0 = fmaxf(m0, rm0), mn1 = fmaxf(m1, rm1);
        float f0 = __expf(m0 - mn0), f1 = __expf(m1 - mn1);
        float ps0 = 0.0f, ps1 = 0.0f;
        #pragma unroll
        for (int nt = 0; nt < 8; nt++) {
            float p0 = __expf(sacc[nt][0] - mn0); sacc[nt][0] = p0; ps0 += p0;
            float p1 = __expf(sacc[nt][1] - mn0); sacc[nt][1] = p1; ps0 += p1;
            float p2 = __expf(sacc[nt][2] - mn1); sacc[nt][2] = p2; ps1 += p2;
            float p3 = __expf(sacc[nt][3] - mn1); sacc[nt][3] = p3; ps1 += p3;
        }
        ps0 += __shfl_xor_sync(0xffffffffu, ps0, 1);
        ps0 += __shfl_xor_sync(0xffffffffu, ps0, 2);
        ps1 += __shfl_xor_sync(0xffffffffu, ps1, 1);
        ps1 += __shfl_xor_sync(0xffffffffu, ps1, 2);
        l0 = l0 * f0 + ps0;
        l1 = l1 * f1 + ps1;
        m0 = mn0; m1 = mn1;
        #pragma unroll
        for (int nt = 0; nt < 8; nt++) {
            oacc[nt][0] *= f0; oacc[nt][1] *= f0;
            oacc[nt][2] *= f1; oacc[nt][3] *= f1;
        }

        #pragma unroll
        for (int kc = 0; kc < 4; kc++) {
            unsigned ah[4], al[4];
            #pragma unroll
            for (int hsel = 0; hsel < 2; hsel++) {
                const float* s0 = sacc[2 * kc + hsel];
                unsigned hi0 = packh2(s0[0], s0[1]);
                unsigned hi1 = packh2(s0[2], s0[3]);
                __half2 h2a = *reinterpret_cast<__half2*>(&hi0);
                __half2 h2b = *reinterpret_cast<__half2*>(&hi1);
                float2 fa = __half22float2(h2a);
                float2 fb = __half22float2(h2b);
                ah[hsel * 2]     = hi0;
                ah[hsel * 2 + 1] = hi1;
                al[hsel * 2]     = packh2(s0[0] - fa.x, s0[1] - fa.y);
                al[hsel * 2 + 1] = packh2(s0[2] - fb.x, s0[3] - fb.y);
            }
            #pragma unroll
            for (int nb = 0; nb < 4; nb++) {
                uint32_t va = boff + (uint32_t)(nb * 16 * FST * 4) + kc * 32;
                unsigned h0, h1, h2, h3, g0, g1, g2, g3;
                LDSM4(h0, h1, h2, h3, vhb + va);
                LDSM4(g0, g1, g2, g3, vlb + va);
                unsigned bh0[2] = {h0, h1}, bh1[2] = {h2, h3};
                unsigned bl0[2] = {g0, g1}, bl1[2] = {g2, g3};
                mma16(oacc[nb * 2],     ah, bh0);
                mma16(oacc[nb * 2],     al, bh0);
                mma16(oacc[nb * 2],     ah, bl0);
                mma16(oacc[nb * 2 + 1], ah, bh1);
                mma16(oacc[nb * 2 + 1], al, bh1);
                mma16(oacc[nb * 2 + 1], ah, bl1);
            }
        }
        buf ^= 1;
    }

    float inv0 = 1.0f / l0, inv1 = 1.0f / l1;
    int row0 = b * SS + i0 + w * 16 + lr;
    unsigned* Ob = O16 + (size_t)row0 * KPD + h * 32;
    #pragma unroll
    for (int nt = 0; nt < 8; nt++) {
        Ob[nt * 4 + lq] = packh2(oacc[nt][0] * inv0, oacc[nt][1] * inv0);
        Ob[(size_t)8 * KPD + nt * 4 + lq] = packh2(oacc[nt][2] * inv1, oacc[nt][3] * inv1);
    }
}

// ---------------- host launcher ----------------
extern "C" void kernel_launch(void* const* d_in, const int* in_sizes, int n_in,
                              void* d_out, int out_size)
{
    const int*   idx   = (const int*)  d_in[0];
    const float* wte   = (const float*)d_in[1];
    const float* wpe   = (const float*)d_in[2];
    const float* ln1_w = (const float*)d_in[3];
    const float* ln1_b = (const float*)d_in[4];
    const float* wq    = (const float*)d_in[5];
    const float* wk    = (const float*)d_in[6];
    const float* wv    = (const float*)d_in[7];
    const float* wo    = (const float*)d_in[8];
    const float* ln2_w = (const float*)d_in[9];
    const float* ln2_b = (const float*)d_in[10];
    const float* fc1   = (const float*)d_in[11];
    const float* fc2   = (const float*)d_in[12];
    const float* lnf_w = (const float*)d_in[13];
    const float* lnf_b = (const float*)d_in[14];
    float* out = (float*)d_out;

    float *x;
    unsigned *q16, *k16, *h16, *tmp16, *ff16, *vph, *vpl;
    unsigned *wq16, *wk16, *wv16, *wo16, *fc116, *fc216, *wte16;
    cudaGetSymbolAddress((void**)&x,     g_x);
    cudaGetSymbolAddress((void**)&q16,   g_q16);
    cudaGetSymbolAddress((void**)&k16,   g_k16);
    cudaGetSymbolAddress((void**)&h16,   g_h16);
    cudaGetSymbolAddress((void**)&tmp16, g_tmp16);
    cudaGetSymbolAddress((void**)&ff16,  g_ff16);
    cudaGetSymbolAddress((void**)&vph,   g_vph);
    cudaGetSymbolAddress((void**)&vpl,   g_vpl);
    cudaGetSymbolAddress((void**)&wq16,  g_wq16);
    cudaGetSymbolAddress((void**)&wk16,  g_wk16);
    cudaGetSymbolAddress((void**)&wv16,  g_wv16);
    cudaGetSymbolAddress((void**)&wo16,  g_wo16);
    cudaGetSymbolAddress((void**)&fc116, g_fc116);
    cudaGetSymbolAddress((void**)&fc216, g_fc216);
    cudaGetSymbolAddress((void**)&wte16, g_wte16);

    const int gs = 3 * STG * 4;      // 110592 bytes
    cudaFuncSetAttribute(mma_gemm<0,false>, cudaFuncAttributeMaxDynamicSharedMemorySize, gs);
    cudaFuncSetAttribute(mma_gemm<1,false>, cudaFuncAttributeMaxDynamicSharedMemorySize, gs);
    cudaFuncSetAttribute(mma_gemm<2,false>, cudaFuncAttributeMaxDynamicSharedMemorySize, gs);
    cudaFuncSetAttribute(mma_gemm<3,false>, cudaFuncAttributeMaxDynamicSharedMemorySize, gs);
    cudaFuncSetAttribute(mma_gemm<0,true>,  cudaFuncAttributeMaxDynamicSharedMemorySize, gs);
    cudaFuncSetAttribute(flash_attn_kernel,
                         cudaFuncAttributeMaxDynamicSharedMemorySize, FA_SMEM_BYTES);

    pack_t<<<dim3(DD / 64, DD / 64, LL), 256>>>(wq, wq16, DD, DD);
    pack_t<<<dim3(DD / 64, DD / 64, LL), 256>>>(wk, wk16, DD, DD);
    pack_t<<<dim3(DD / 64, DD / 64, LL), 256>>>(wv, wv16, DD, DD);
    pack_t<<<dim3(DD / 64, DD / 64, LL), 256>>>(wo, wo16, DD, DD);
    pack_t<<<dim3(DFF / 64, DD / 64, LL), 256>>>(fc1, fc116, DD, DFF);
    pack_t<<<dim3(DD / 64, DFF / 64, LL), 256>>>(fc2, fc216, DFF, DD);
    {
        int tE = VV * KPD;
        pack_nk<<<(tE + 255) / 256, 256>>>(wte, wte16, tE);
    }

    embed_kernel<<<NTOK, 256>>>(idx, wte, wpe, x);

    dim3 gQKV(DD / 128, NTOK / 128, 3);
    dim3 gD  (DD / 128, NTOK / 128, 1);
    dim3 gF  (DFF / 128, NTOK / 128, 1);

    for (int l = 0; l < LL; l++) {
        unsigned* Wq = wq16 + (size_t)l * DD * KPD;
        unsigned* Wk = wk16 + (size_t)l * DD * KPD;
        unsigned* Wv = wv16 + (size_t)l * DD * KPD;
        unsigned* Wo = wo16 + (size_t)l * DD * KPD;
        unsigned* W1 = fc116 + (size_t)l * DFF * KPD;
        unsigned* W2 = fc216 + (size_t)l * DD * KPF;

        layernorm_kernel<<<NTOK, 256>>>(x, ln1_w + l * DD, ln1_b + l * DD, h16);

        // q -> q16, k -> k16, v -> fused transpose into vph/vpl
        mma_gemm<3,false><<<gQKV, 256, gs>>>(h16, Wq, Wk, Wv, nullptr,
                                             q16, (float*)k16, vph, vpl, DD, DD);

        flash_attn_kernel<<<dim3(SS / 64, BB * HH), 128, FA_SMEM_BYTES>>>(
            q16, k16, vph, vpl, tmp16);

        mma_gemm<1,false><<<gD, 256, gs>>>(tmp16, Wo, Wo, Wo, x, x,
                                           nullptr, nullptr, nullptr, DD, DD);

        layernorm_kernel<<<NTOK, 256>>>(x, ln2_w + l * DD, ln2_b + l * DD, h16);
        mma_gemm<2,false><<<gF, 256, gs>>>(h16, W1, W1, W1, nullptr, ff16,
                                           nullptr, nullptr, nullptr, DFF, DD);
        mma_gemm<1,false><<<gD, 256, gs>>>(ff16, W2, W2, W2, x, x,
                                           nullptr, nullptr, nullptr, DD, DFF);
    }

    layernorm_kernel<<<NTOK, 256>>>(x, lnf_w, lnf_b, h16);
    mma_gemm<0,true><<<dim3((VV + 127) / 128, NTOK / 128, 1), 256, gs>>>(
        h16, wte16, wte16, wte16, nullptr, out, nullptr, nullptr, nullptr, VV, DD);
}

// round 15
// speedup vs baseline: 1.0484x; 1.0063x over previous
#include <cuda_runtime.h>
#include <cuda_bf16.h>
#include <cuda_fp16.h>
#include <math.h>
#include <stdint.h>

// ---------------- problem constants ----------------
#define BB 4
#define SS 1024
#define LL 12
#define DD 768
#define HH 12
#define DKK 64
#define DFF 3072
#define VV 50257
#define NTOK (BB*SS)          // 4096
#define KPD (DD/2)            // 384
#define KPF (DFF/2)           // 1536

// ---------------- scratch (device globals; no allocs allowed) --------------
__device__ unsigned g_q16 [(size_t)NTOK * KPD];
__device__ unsigned g_k16 [(size_t)NTOK * KPD];
__device__ unsigned g_h16 [(size_t)NTOK * KPD];
__device__ unsigned g_tmp16[(size_t)NTOK * KPD];
__device__ unsigned g_ff16 [(size_t)NTOK * KPF];
__device__ float    g_x   [(size_t)NTOK * DD];
__device__ unsigned g_vph [(size_t)BB * HH * DKK * (SS/2)];
__device__ unsigned g_vpl [(size_t)BB * HH * DKK * (SS/2)];
// packed fp16 weights, K-major: [L][N][K/2] half2 words
__device__ unsigned g_wq16 [(size_t)LL * DD * KPD];
__device__ unsigned g_wk16 [(size_t)LL * DD * KPD];
__device__ unsigned g_wv16 [(size_t)LL * DD * KPD];
__device__ unsigned g_wo16 [(size_t)LL * DD * KPD];
__device__ unsigned g_fc116[(size_t)LL * DFF * KPD];
__device__ unsigned g_fc216[(size_t)LL * DD * KPF];
__device__ unsigned g_wte16[(size_t)VV * KPD];

// ---------------- helpers ----------------
__device__ __forceinline__ uint32_t smem_u32(const void* p) {
    uint32_t a;
    asm("{ .reg .u64 t; cvta.to.shared.u64 t, %1; cvt.u32.u64 %0, t; }"
        : "=r"(a) : "l"(p));
    return a;
}
__device__ __forceinline__ void mma16(float* d, const unsigned* a, const unsigned* b) {
    asm volatile(
        "mma.sync.aligned.m16n8k16.row.col.f32.f16.f16.f32 "
        "{%0,%1,%2,%3},{%4,%5,%6,%7},{%8,%9},{%0,%1,%2,%3};"
        : "+f"(d[0]), "+f"(d[1]), "+f"(d[2]), "+f"(d[3])
        : "r"(a[0]), "r"(a[1]), "r"(a[2]), "r"(a[3]), "r"(b[0]), "r"(b[1]));
}
#define LDSM4(r0, r1, r2, r3, addr) \
    asm volatile("ldmatrix.sync.aligned.m8n8.x4.shared.b16 {%0,%1,%2,%3}, [%4];" \
                 : "=r"(r0), "=r"(r1), "=r"(r2), "=r"(r3) : "r"(addr))
__device__ __forceinline__ unsigned packh2(float lo, float hi) {
    __half2 h = __floats2half2_rn(lo, hi);
    return *reinterpret_cast<unsigned*>(&h);
}
__device__ __forceinline__ void cp16(uint32_t d, const void* g) {
    asm volatile("cp.async.cg.shared.global [%0], [%1], 16;" :: "r"(d), "l"(g));
}
__device__ __forceinline__ void cp16g(uint32_t d, const void* g, int sz) {
    asm volatile("cp.async.cg.shared.global [%0], [%1], 16, %2;"
                 :: "r"(d), "l"(g), "r"(sz));
}

// ---------------- weight packing (once per replay) ----------------
__global__ void pack_t(const float* __restrict__ W, unsigned* __restrict__ out,
                       int K, int N)
{
    __shared__ float t[64][65];
    const int n0 = blockIdx.x * 64, k0 = blockIdx.y * 64, l = blockIdx.z;
    const float* Wl = W + (size_t)l * K * N;
    unsigned* ol = out + (size_t)l * N * (K >> 1);
    const int tid = threadIdx.x;
    #pragma unroll
    for (int p = 0; p < 16; p++) {
        int idx = tid + p * 256;
        int kk = idx >> 6, nn = idx & 63;
        t[kk][nn] = Wl[(size_t)(k0 + kk) * N + n0 + nn];
    }
    __syncthreads();
    #pragma unroll
    for (int p = 0; p < 8; p++) {
        int idx = tid + p * 256;
        int nn = idx >> 5, kp = idx & 31;
        ol[(size_t)(n0 + nn) * (K >> 1) + (k0 >> 1) + kp] =
            packh2(t[2 * kp][nn], t[2 * kp + 1][nn]);
    }
}
__global__ void pack_nk(const float* __restrict__ W, unsigned* __restrict__ out,
                        int total)
{
    int i = blockIdx.x * 256 + threadIdx.x;
    if (i >= total) return;
    int v = i / KPD, kp = i - v * KPD;
    float2 f = *(const float2*)(W + (size_t)v * DD + 2 * kp);
    out[i] = packh2(f.x, f.y);
}

// ---------------- fp16 NT GEMM: 8 warps, BK=64, 3-stage, templated M-tile --
// EPI: 0 none->f32, 1 +Cin->f32, 2 GELU->packed fp16,
//      3 QKV: z0->q16, z1->k16, z2->fused V transpose to vph/vpl (MT=128 only)
// NG: guard N (head gemm; N odd -> scalar stores only)
// MT: CTA M-tile rows (128 or 64); warp tile (MT/2)x32.
#define APAD 36

template<int EPI, bool NG, int MT>
__global__ __launch_bounds__(256, 2)
void mma_gemm(const unsigned* __restrict__ A,
              const unsigned* __restrict__ B0, const unsigned* __restrict__ B1,
              const unsigned* __restrict__ B2,
              const float* __restrict__ Cin, void* __restrict__ Cv,
              float* __restrict__ C1f,
              unsigned* __restrict__ Vh, unsigned* __restrict__ Vl,
              int N, int K)
{
    extern __shared__ unsigned gsm[];
    constexpr int AWRD = MT * APAD;            // A tile words
    constexpr int STGW = (MT + 128) * APAD;    // stage words
    constexpr int MTC  = MT / 32;              // mt count per warp

    const unsigned* B = (blockIdx.z == 0) ? B0 : ((blockIdx.z == 1) ? B1 : B2);
    float* Cf = (blockIdx.z == 0) ? (float*)Cv : C1f;
    unsigned* C16 = (unsigned*)Cv;

    const int tid  = threadIdx.x;
    const int lane = tid & 31;
    const int warp = tid >> 5;
    const int wm = warp >> 2, wn = warp & 3;       // 2 x 4
    const int lr = lane >> 2, lq = lane & 3;
    const int m0 = blockIdx.y * MT;
    const int n0 = blockIdx.x * 128;
    const int KA = K >> 1;

    const uint32_t sbase = smem_u32(gsm);
    const int lrow = lane & 7, lg = lane >> 3;
    const uint32_t aoff = (uint32_t)(((wm * (MT / 2) + (lg & 1) * 8 + lrow) * APAD
                                      + (lg >> 1) * 4) * 4);
    const uint32_t boff = (uint32_t)(((wn * 32 + (lg >> 1) * 8 + lrow) * APAD
                                      + (lg & 1) * 4) * 4);

    float acc[MTC][4][4];
    #pragma unroll
    for (int i = 0; i < MTC; i++)
        #pragma unroll
        for (int j = 0; j < 4; j++)
            #pragma unroll
            for (int t = 0; t < 4; t++) acc[i][j][t] = 0.0f;

    auto load_stage = [&](int stg) {
        const int slot = stg % 3;
        const uint32_t sa = sbase + (uint32_t)(slot * STGW) * 4u;
        const uint32_t sb = sa + (uint32_t)AWRD * 4u;
        const int kp0 = stg * 32;
        #pragma unroll
        for (int p = 0; p < MT / 32; p++) {        // A: MT*32 words
            int s = tid + p * 256;
            int r = s >> 3, c4 = (s & 7) * 4;
            cp16(sa + (uint32_t)(r * APAD + c4) * 4u,
                 A + (size_t)(m0 + r) * KA + kp0 + c4);
        }
        #pragma unroll
        for (int p = 0; p < 4; p++) {              // B: 128*32 words
            int s = tid + p * 256;
            int r = s >> 3, c4 = (s & 7) * 4;
            if (NG) {
                int n = n0 + r;
                int ok = (n < N);
                cp16g(sb + (uint32_t)(r * APAD + c4) * 4u,
                      B + (size_t)(ok ? n : 0) * KA + kp0 + c4, ok ? 16 : 0);
            } else {
                cp16(sb + (uint32_t)(r * APAD + c4) * 4u,
                     B + (size_t)(n0 + r) * KA + kp0 + c4);
            }
        }
        asm volatile("cp.async.commit_group;" ::: "memory");
    };

    auto compute = [&](int slot) {
        const uint32_t sa = sbase + (uint32_t)(slot * STGW) * 4u;
        const uint32_t sb = sa + (uint32_t)AWRD * 4u;
        #pragma unroll
        for (int kc = 0; kc < 4; kc++) {
            const uint32_t kbb = (uint32_t)(kc * 32);
            unsigned af[MTC][4];
            #pragma unroll
            for (int mt = 0; mt < MTC; mt++) {
                uint32_t addr = sa + aoff + kbb + (uint32_t)(mt * 16 * APAD * 4);
                LDSM4(af[mt][0], af[mt][1], af[mt][2], af[mt][3], addr);
            }
            unsigned bf[4][2];
            #pragma unroll
            for (int np = 0; np < 2; np++) {
                uint32_t addr = sb + boff + kbb + (uint32_t)(np * 16 * APAD * 4);
                unsigned r0, r1, r2, r3;
                LDSM4(r0, r1, r2, r3, addr);
                bf[np * 2][0] = r0;     bf[np * 2][1] = r1;
                bf[np * 2 + 1][0] = r2; bf[np * 2 + 1][1] = r3;
            }
            #pragma unroll
            for (int mt = 0; mt < MTC; mt++)
                #pragma unroll
                for (int nt = 0; nt < 4; nt++)
                    mma16(acc[mt][nt], af[mt], bf[nt]);
        }
    };

    const int nIter = K >> 6;
    load_stage(0);
    load_stage(1);
    for (int it = 0; it < nIter; it++) {
        if (it + 1 < nIter) asm volatile("cp.async.wait_group 1;" ::: "memory");
        else                asm volatile("cp.async.wait_group 0;" ::: "memory");
        __syncthreads();
        if (it + 2 < nIter) load_stage(it + 2);
        compute(it % 3);
    }

    // ---- fused V transpose epilogue (EPI==3, z==2; MT=128 only) ----
    if (EPI == 3 && MT == 128) {
        if (blockIdx.z == 2) {
            float* st = (float*)gsm;           // [128][129] f32
            __syncthreads();
            #pragma unroll
            for (int mt = 0; mt < MTC; mt++) {
                int r = wm * (MT / 2) + mt * 16 + lr;
                #pragma unroll
                for (int nt = 0; nt < 4; nt++) {
                    int c = wn * 32 + nt * 8 + lq * 2;
                    float* a4 = acc[mt][nt];
                    st[r * 129 + c]           = a4[0];
                    st[r * 129 + c + 1]       = a4[1];
                    st[(r + 8) * 129 + c]     = a4[2];
                    st[(r + 8) * 129 + c + 1] = a4[3];
                }
            }
            __syncthreads();
            const int b  = m0 / SS;
            const int j0 = m0 & (SS - 1);
            #pragma unroll
            for (int p = 0; p < 32; p++) {
                int idx = tid + p * 256;
                int cc = idx >> 6, jp = idx & 63;
                float v0 = st[(2 * jp) * 129 + cc];
                float v1 = st[(2 * jp + 1) * 129 + cc];
                unsigned hi = packh2(v0, v1);
                __half2 hh = *reinterpret_cast<__half2*>(&hi);
                float2 fh = __half22float2(hh);
                unsigned lo = packh2(v0 - fh.x, v1 - fh.y);
                int h  = (n0 + cc) >> 6;
                int dk = (n0 + cc) & 63;
                size_t o = ((size_t)(b * HH + h) * DKK + dk) * (SS / 2)
                           + (j0 >> 1) + jp;
                Vh[o] = hi;
                Vl[o] = lo;
            }
            return;
        }
    }

    // ---- standard epilogues ----
    #pragma unroll
    for (int mt = 0; mt < MTC; mt++) {
        int r0 = m0 + wm * (MT / 2) + mt * 16 + lr;
        #pragma unroll
        for (int nt = 0; nt < 4; nt++) {
            int col = n0 + wn * 32 + nt * 8 + lq * 2;
            float* a4 = acc[mt][nt];
            float v00 = a4[0], v01 = a4[1], v10 = a4[2], v11 = a4[3];
            if (EPI == 2) {
                v00 = 0.5f * v00 * (1.0f + erff(v00 * 0.70710678118654752f));
                v01 = 0.5f * v01 * (1.0f + erff(v01 * 0.70710678118654752f));
                v10 = 0.5f * v10 * (1.0f + erff(v10 * 0.70710678118654752f));
                v11 = 0.5f * v11 * (1.0f + erff(v11 * 0.70710678118654752f));
                int nw = N >> 1;
                C16[(size_t)r0 * nw + (col >> 1)]       = packh2(v00, v01);
                C16[(size_t)(r0 + 8) * nw + (col >> 1)] = packh2(v10, v11);
            } else if (EPI == 3) {
                unsigned* o = (blockIdx.z == 0) ? (unsigned*)Cv : (unsigned*)C1f;
                int nw = N >> 1;
                o[(size_t)r0 * nw + (col >> 1)]       = packh2(v00, v01);
                o[(size_t)(r0 + 8) * nw + (col >> 1)] = packh2(v10, v11);
            } else {
                size_t o0 = (size_t)r0 * N + col;
                size_t o1 = (size_t)(r0 + 8) * N + col;
                if (EPI == 1) {
                    float2 c0 = *(const float2*)(Cin + o0);
                    float2 c1 = *(const float2*)(Cin + o1);
                    v00 += c0.x; v01 += c0.y; v10 += c1.x; v11 += c1.y;
                }
                if (!NG) {
                    *(float2*)(Cf + o0) = make_float2(v00, v01);
                    *(float2*)(Cf + o1) = make_float2(v10, v11);
                } else {
                    // N odd (head gemm): scalar stores only.
                    if (col < N)     { Cf[o0] = v00;     Cf[o1] = v10; }
                    if (col + 1 < N) { Cf[o0 + 1] = v01; Cf[o1 + 1] = v11; }
                }
            }
        }
    }
}

// ---------------- embedding ----------------
__global__ void embed_kernel(const int* __restrict__ idx,
                             const float* __restrict__ wte,
                             const float* __restrict__ wpe,
                             float* __restrict__ x)
{
    int row = blockIdx.x;
    int s   = row & (SS - 1);
    int tok = idx[row];
    int tid = threadIdx.x;
    #pragma unroll
    for (int l = 0; l < 3; l++) {
        int d = tid + l * 256;
        x[(size_t)row * DD + d] = wte[(size_t)tok * DD + d] + wpe[(size_t)s * DD + d];
    }
}

// ---------------- layernorm -> packed fp16 (shuffle reductions) ------------
__global__ void layernorm_kernel(const float* __restrict__ x,
                                 const float* __restrict__ w,
                                 const float* __restrict__ b,
                                 unsigned* __restrict__ y16)
{
    int row = blockIdx.x;
    const float2* p2 = (const float2*)(x + (size_t)row * DD);
    int tid = threadIdx.x;                 // 256
    int lane = tid & 31, wid = tid >> 5;
    float2 f1 = p2[tid];
    float2 f2 = (tid < 128) ? p2[tid + 256] : make_float2(0.f, 0.f);

    __shared__ float ws[8], ws2[8];
    float s = f1.x + f1.y + f2.x + f2.y;
    #pragma unroll
    for (int o = 16; o > 0; o >>= 1) s += __shfl_xor_sync(0xffffffffu, s, o);
    if (lane == 0) ws[wid] = s;
    __syncthreads();
    float mean = (ws[0] + ws[1] + ws[2] + ws[3] + ws[4] + ws[5] + ws[6] + ws[7])
                 * (1.0f / DD);

    float a0 = f1.x - mean, a1 = f1.y - mean;
    float a2 = f2.x - mean, a3 = f2.y - mean;
    float sq = a0 * a0 + a1 * a1 + ((tid < 128) ? (a2 * a2 + a3 * a3) : 0.f);
    #pragma unroll
    for (int o = 16; o > 0; o >>= 1) sq += __shfl_xor_sync(0xffffffffu, sq, o);
    if (lane == 0) ws2[wid] = sq;
    __syncthreads();
    float var = (ws2[0] + ws2[1] + ws2[2] + ws2[3] + ws2[4] + ws2[5] + ws2[6] + ws2[7])
                * (1.0f / DD);
    float rstd = rsqrtf(var + 1e-5f);

    const float2* w2 = (const float2*)w;
    const float2* b2 = (const float2*)b;
    unsigned* yr = y16 + (size_t)row * KPD;
    {
        float2 ww = w2[tid], bb = b2[tid];
        yr[tid] = packh2(a0 * rstd * ww.x + bb.x, a1 * rstd * ww.y + bb.y);
    }
    if (tid < 128) {
        float2 ww = w2[tid + 256], bb = b2[tid + 256];
        yr[tid + 256] = packh2(a2 * rstd * ww.x + bb.x, a3 * rstd * ww.y + bb.y);
    }
}

// ---------------- fused flash attention (fp16, double-buffered KV) ---------
#define FST 36
#define FQW (64 * FST)
#define FBW (3 * 64 * FST)
#define FA_SMEM_BYTES ((FQW + 2 * FBW) * 4)   // 64512

__global__ __launch_bounds__(128, 3)
void flash_attn_kernel(const unsigned* __restrict__ q16,
                       const unsigned* __restrict__ k16,
                       const unsigned* __restrict__ vph,
                       const unsigned* __restrict__ vpl,
                       unsigned* __restrict__ O16)
{
    extern __shared__ unsigned fsm[];

    const int tid  = threadIdx.x;
    const int lane = tid & 31;
    const int w    = tid >> 5;
    const int lr   = lane >> 2;
    const int lq   = lane & 3;
    const int it   = (SS / 64 - 1) - blockIdx.x;
    const int bh   = blockIdx.y;
    const int b    = bh / HH, h = bh % HH;
    const int i0   = it * 64;
    const int lrow = lane & 7, lg = lane >> 3;

    const uint32_t sQb = smem_u32(fsm);
    const uint32_t aoff = (uint32_t)(((w * 16 + (lg & 1) * 8 + lrow) * FST
                                      + (lg >> 1) * 4) * 4);
    const uint32_t boff = (uint32_t)((((lg >> 1) * 8 + lrow) * FST
                                      + (lg & 1) * 4) * 4);

    auto load_tile = [&](int j0, int buf) {
        const uint32_t kb  = sQb + (uint32_t)(FQW + buf * FBW) * 4u;
        const uint32_t vhb = kb + (uint32_t)(64 * FST) * 4u;
        const uint32_t vlb = vhb + (uint32_t)(64 * FST) * 4u;
        #pragma unroll
        for (int p = 0; p < 4; p++) {
            int s = tid + p * 128;
            int r = s >> 3, c4 = (s & 7) * 4;
            cp16(kb + (uint32_t)(r * FST + c4) * 4u,
                 k16 + (size_t)(b * SS + j0 + r) * KPD + h * 32 + c4);
            size_t vo = ((size_t)bh * DKK + r) * (SS / 2) + (j0 >> 1) + c4;
            cp16(vhb + (uint32_t)(r * FST + c4) * 4u, vph + vo);
            cp16(vlb + (uint32_t)(r * FST + c4) * 4u, vpl + vo);
        }
        asm volatile("cp.async.commit_group;" ::: "memory");
    };

    #pragma unroll
    for (int p = 0; p < 4; p++) {
        int s = tid + p * 128;
        int r = s >> 3, c4 = (s & 7) * 4;
        cp16(sQb + (uint32_t)(r * FST + c4) * 4u,
             q16 + (size_t)(b * SS + i0 + r) * KPD + h * 32 + c4);
    }
    asm volatile("cp.async.commit_group;" ::: "memory");
    load_tile(0, 0);
    asm volatile("cp.async.wait_group 1;" ::: "memory");
    __syncthreads();

    unsigned qf[4][4];
    #pragma unroll
    for (int kc = 0; kc < 4; kc++)
        LDSM4(qf[kc][0], qf[kc][1], qf[kc][2], qf[kc][3], sQb + aoff + kc * 32);

    float oacc[8][4];
    #pragma unroll
    for (int nt = 0; nt < 8; nt++)
        #pragma unroll
        for (int e = 0; e < 4; e++) oacc[nt][e] = 0.0f;
    float m0 = -1e30f, m1 = -1e30f, l0 = 0.0f, l1 = 0.0f;

    int buf = 0;
    for (int j0 = 0; j0 <= i0; j0 += 64) {
        __syncthreads();
        const bool more = (j0 + 64 <= i0);
        if (more) load_tile(j0 + 64, buf ^ 1);
        if (more) asm volatile("cp.async.wait_group 1;" ::: "memory");
        else      asm volatile("cp.async.wait_group 0;" ::: "memory");
        __syncthreads();

        const uint32_t kb  = sQb + (uint32_t)(FQW + buf * FBW) * 4u;
        const uint32_t vhb = kb + (uint32_t)(64 * FST) * 4u;
        const uint32_t vlb = vhb + (uint32_t)(64 * FST) * 4u;

        float sacc[8][4];
        #pragma unroll
        for (int nt = 0; nt < 8; nt++)
            #pragma unroll
            for (int e = 0; e < 4; e++) sacc[nt][e] = 0.0f;
        #pragma unroll
        for (int kc = 0; kc < 4; kc++) {
            #pragma unroll
            for (int nb = 0; nb < 4; nb++) {
                unsigned r0, r1, r2, r3;
                LDSM4(r0, r1, r2, r3,
                      kb + boff + (uint32_t)(nb * 16 * FST * 4) + kc * 32);
                unsigned b0[2] = {r0, r1}, b1[2] = {r2, r3};
                mma16(sacc[nb * 2],     qf[kc], b0);
                mma16(sacc[nb * 2 + 1], qf[kc], b1);
            }
        }

        #pragma unroll
        for (int nt = 0; nt < 8; nt++)
            #pragma unroll
            for (int e = 0; e < 4; e++) sacc[nt][e] *= 0.125f;
        if (j0 == i0) {
            int ii0 = w * 16 + lr, ii1 = ii0 + 8;
            #pragma unroll
            for (int nt = 0; nt < 8; nt++) {
                int jj = nt * 8 + 2 * lq;
                if (jj     > ii0) sacc[nt][0] = -1e30f;
                if (jj + 1 > ii0) sacc[nt][1] = -1e30f;
                if (jj     > ii1) sacc[nt][2] = -1e30f;
                if (jj + 1 > ii1) sacc[nt][3] = -1e30f;
            }
        }

        float rm0 = -1e30f, rm1 = -1e30f;
        #pragma unroll
        for (int nt = 0; nt < 8; nt++) {
            rm0 = fmaxf(rm0, fmaxf(sacc[nt][0], sacc[nt][1]));
            rm1 = fmaxf(rm1, fmaxf(sacc[nt][2], sacc[nt][3]));
        }
        rm0 = fmaxf(rm0, __shfl_xor_sync(0xffffffffu, rm0, 1));
        rm0 = fmaxf(rm0, __shfl_xor_sync(0xffffffffu, rm0, 2));
        rm1 = fmaxf(rm1, __shfl_xor_sync(0xffffffffu, rm1, 1));
        rm1 = fmaxf(rm1, __shfl_xor_sync(0xffffffffu, rm1, 2));
        float mn0 = fmaxf(m0, rm0), mn1 = fmaxf(m1, rm1);
        float f0 = __expf(m0 - mn0), f1 = __expf(m1 - mn1);
        float ps0 = 0.0f, ps1 = 0.0f;
        #pragma unroll
        for (int nt = 0; nt < 8; nt++) {
            float p0 = __expf(sacc[nt][0] - mn0); sacc[nt][0] = p0; ps0 += p0;
            float p1 = __expf(sacc[nt][1] - mn0); sacc[nt][1] = p1; ps0 += p1;
            float p2 = __expf(sacc[nt][2] - mn1); sacc[nt][2] = p2; ps1 += p2;
            float p3 = __expf(sacc[nt][3] - mn1); sacc[nt][3] = p3; ps1 += p3;
        }
        ps0 += __shfl_xor_sync(0xffffffffu, ps0, 1);
        ps0 += __shfl_xor_sync(0xffffffffu, ps0, 2);
        ps1 += __shfl_xor_sync(0xffffffffu, ps1, 1);
        ps1 += __shfl_xor_sync(0xffffffffu, ps1, 2);
        l0 = l0 * f0 + ps0;
        l1 = l1 * f1 + ps1;
        m0 = mn0; m1 = mn1;
        #pragma unroll
        for (int nt = 0; nt < 8; nt++) {
            oacc[nt][0] *= f0; oacc[nt][1] *= f0;
            oacc[nt][2] *= f1; oacc[nt][3] *= f1;
        }

        #pragma unroll
        for (int kc = 0; kc < 4; kc++) {
            unsigned ah[4], al[4];
            #pragma unroll
            for (int hsel = 0; hsel < 2; hsel++) {
                const float* s0 = sacc[2 * kc + hsel];
                unsigned hi0 = packh2(s0[0], s0[1]);
                unsigned hi1 = packh2(s0[2], s0[3]);
                __half2 h2a = *reinterpret_cast<__half2*>(&hi0);
                __half2 h2b = *reinterpret_cast<__half2*>(&hi1);
                float2 fa = __half22float2(h2a);
                float2 fb = __half22float2(h2b);
                ah[hsel * 2]     = hi0;
                ah[hsel * 2 + 1] = hi1;
                al[hsel * 2]     = packh2(s0[0] - fa.x, s0[1] - fa.y);
                al[hsel * 2 + 1] = packh2(s0[2] - fb.x, s0[3] - fb.y);
            }
            #pragma unroll
            for (int nb = 0; nb < 4; nb++) {
                uint32_t va = boff + (uint32_t)(nb * 16 * FST * 4) + kc * 32;
                unsigned h0, h1, h2, h3, g0, g1, g2, g3;
                LDSM4(h0, h1, h2, h3, vhb + va);
                LDSM4(g0, g1, g2, g3, vlb + va);
                unsigned bh0[2] = {h0, h1}, bh1[2] = {h2, h3};
                unsigned bl0[2] = {g0, g1}, bl1[2] = {g2, g3};
                mma16(oacc[nb * 2],     ah, bh0);
                mma16(oacc[nb * 2],     al, bh0);
                mma16(oacc[nb * 2],     ah, bl0);
                mma16(oacc[nb * 2 + 1], ah, bh1);
                mma16(oacc[nb * 2 + 1], al, bh1);
                mma16(oacc[nb * 2 + 1], ah, bl1);
            }
        }
        buf ^= 1;
    }

    float inv0 = 1.0f / l0, inv1 = 1.0f / l1;
    int row0 = b * SS + i0 + w * 16 + lr;
    unsigned* Ob = O16 + (size_t)row0 * KPD + h * 32;
    #pragma unroll
    for (int nt = 0; nt < 8; nt++) {
        Ob[nt * 4 + lq] = packh2(oacc[nt][0] * inv0, oacc[nt][1] * inv0);
        Ob[(size_t)8 * KPD + nt * 4 + lq] = packh2(oacc[nt][2] * inv1, oacc[nt][3] * inv1);
    }
}

// ---------------- host launcher ----------------
extern "C" void kernel_launch(void* const* d_in, const int* in_sizes, int n_in,
                              void* d_out, int out_size)
{
    const int*   idx   = (const int*)  d_in[0];
    const float* wte   = (const float*)d_in[1];
    const float* wpe   = (const float*)d_in[2];
    const float* ln1_w = (const float*)d_in[3];
    const float* ln1_b = (const float*)d_in[4];
    const float* wq    = (const float*)d_in[5];
    const float* wk    = (const float*)d_in[6];
    const float* wv    = (const float*)d_in[7];
    const float* wo    = (const float*)d_in[8];
    const float* ln2_w = (const float*)d_in[9];
    const float* ln2_b = (const float*)d_in[10];
    const float* fc1   = (const float*)d_in[11];
    const float* fc2   = (const float*)d_in[12];
    const float* lnf_w = (const float*)d_in[13];
    const float* lnf_b = (const float*)d_in[14];
    float* out = (float*)d_out;

    float *x;
    unsigned *q16, *k16, *h16, *tmp16, *ff16, *vph, *vpl;
    unsigned *wq16, *wk16, *wv16, *wo16, *fc116, *fc216, *wte16;
    cudaGetSymbolAddress((void**)&x,     g_x);
    cudaGetSymbolAddress((void**)&q16,   g_q16);
    cudaGetSymbolAddress((void**)&k16,   g_k16);
    cudaGetSymbolAddress((void**)&h16,   g_h16);
    cudaGetSymbolAddress((void**)&tmp16, g_tmp16);
    cudaGetSymbolAddress((void**)&ff16,  g_ff16);
    cudaGetSymbolAddress((void**)&vph,   g_vph);
    cudaGetSymbolAddress((void**)&vpl,   g_vpl);
    cudaGetSymbolAddress((void**)&wq16,  g_wq16);
    cudaGetSymbolAddress((void**)&wk16,  g_wk16);
    cudaGetSymbolAddress((void**)&wv16,  g_wv16);
    cudaGetSymbolAddress((void**)&wo16,  g_wo16);
    cudaGetSymbolAddress((void**)&fc116, g_fc116);
    cudaGetSymbolAddress((void**)&fc216, g_fc216);
    cudaGetSymbolAddress((void**)&wte16, g_wte16);

    const int gs128 = 3 * (256 * APAD) * 4;    // 110592 bytes
    const int gs64  = 3 * (192 * APAD) * 4;    // 82944 bytes
    cudaFuncSetAttribute(mma_gemm<1,false,128>, cudaFuncAttributeMaxDynamicSharedMemorySize, gs128);
    cudaFuncSetAttribute(mma_gemm<2,false,128>, cudaFuncAttributeMaxDynamicSharedMemorySize, gs128);
    cudaFuncSetAttribute(mma_gemm<3,false,128>, cudaFuncAttributeMaxDynamicSharedMemorySize, gs128);
    cudaFuncSetAttribute(mma_gemm<0,true,128>,  cudaFuncAttributeMaxDynamicSharedMemorySize, gs128);
    cudaFuncSetAttribute(mma_gemm<1,false,64>,  cudaFuncAttributeMaxDynamicSharedMemorySize, gs64);
    cudaFuncSetAttribute(flash_attn_kernel,
                         cudaFuncAttributeMaxDynamicSharedMemorySize, FA_SMEM_BYTES);

    pack_t<<<dim3(DD / 64, DD / 64, LL), 256>>>(wq, wq16, DD, DD);
    pack_t<<<dim3(DD / 64, DD / 64, LL), 256>>>(wk, wk16, DD, DD);
    pack_t<<<dim3(DD / 64, DD / 64, LL), 256>>>(wv, wv16, DD, DD);
    pack_t<<<dim3(DD / 64, DD / 64, LL), 256>>>(wo, wo16, DD, DD);
    pack_t<<<dim3(DFF / 64, DD / 64, LL), 256>>>(fc1, fc116, DD, DFF);
    pack_t<<<dim3(DD / 64, DFF / 64, LL), 256>>>(fc2, fc216, DFF, DD);
    {
        int tE = VV * KPD;
        pack_nk<<<(tE + 255) / 256, 256>>>(wte, wte16, tE);
    }

    embed_kernel<<<NTOK, 256>>>(idx, wte, wpe, x);

    dim3 gQKV(DD / 128, NTOK / 128, 3);
    dim3 gD64(DD / 128, NTOK / 64, 1);      // (6, 64) for wo / fc2
    dim3 gF  (DFF / 128, NTOK / 128, 1);

    for (int l = 0; l < LL; l++) {
        unsigned* Wq = wq16 + (size_t)l * DD * KPD;
        unsigned* Wk = wk16 + (size_t)l * DD * KPD;
        unsigned* Wv = wv16 + (size_t)l * DD * KPD;
        unsigned* Wo = wo16 + (size_t)l * DD * KPD;
        unsigned* W1 = fc116 + (size_t)l * DFF * KPD;
        unsigned* W2 = fc216 + (size_t)l * DD * KPF;

        layernorm_kernel<<<NTOK, 256>>>(x, ln1_w + l * DD, ln1_b + l * DD, h16);

        // q -> q16, k -> k16, v -> fused transpose into vph/vpl
        mma_gemm<3,false,128><<<gQKV, 256, gs128>>>(h16, Wq, Wk, Wv, nullptr,
                                                    q16, (float*)k16, vph, vpl,
                                                    DD, DD);

        flash_attn_kernel<<<dim3(SS / 64, BB * HH), 128, FA_SMEM_BYTES>>>(
            q16, k16, vph, vpl, tmp16);

        mma_gemm<1,false,64><<<gD64, 256, gs64>>>(tmp16, Wo, Wo, Wo, x, x,
                                                  nullptr, nullptr, nullptr,
                                                  DD, DD);

        layernorm_kernel<<<NTOK, 256>>>(x, ln2_w + l * DD, ln2_b + l * DD, h16);
        mma_gemm<2,false,128><<<gF, 256, gs128>>>(h16, W1, W1, W1, nullptr, ff16,
                                                  nullptr, nullptr, nullptr,
                                                  DFF, DD);
        mma_gemm<1,false,64><<<gD64, 256, gs64>>>(ff16, W2, W2, W2, x, x,
                                                  nullptr, nullptr, nullptr,
                                                  DD, DFF);
    }

    layernorm_kernel<<<NTOK, 256>>>(x, lnf_w, lnf_b, h16);
    mma_gemm<0,true,128><<<dim3((VV + 127) / 128, NTOK / 128, 1), 256, gs128>>>(
        h16, wte16, wte16, wte16, nullptr, out, nullptr, nullptr, nullptr, VV, DD);
}

// round 16
// speedup vs baseline: 1.0608x; 1.0118x over previous
#include <cuda_runtime.h>
#include <cuda_bf16.h>
#include <cuda_fp16.h>
#include <math.h>
#include <stdint.h>

// ---------------- problem constants ----------------
#define BB 4
#define SS 1024
#define LL 12
#define DD 768
#define HH 12
#define DKK 64
#define DFF 3072
#define VV 50257
#define NTOK (BB*SS)          // 4096
#define KPD (DD/2)            // 384
#define KPF (DFF/2)           // 1536

// ---------------- scratch (device globals; no allocs allowed) --------------
__device__ unsigned g_q16 [(size_t)NTOK * KPD];
__device__ unsigned g_k16 [(size_t)NTOK * KPD];
__device__ unsigned g_h16 [(size_t)NTOK * KPD];
__device__ unsigned g_tmp16[(size_t)NTOK * KPD];
__device__ unsigned g_ff16 [(size_t)NTOK * KPF];
__device__ float    g_x   [(size_t)NTOK * DD];
__device__ unsigned g_vph [(size_t)BB * HH * DKK * (SS/2)];
__device__ unsigned g_vpl [(size_t)BB * HH * DKK * (SS/2)];
// packed fp16 weights, K-major: [L][N][K/2] half2 words
__device__ unsigned g_wq16 [(size_t)LL * DD * KPD];
__device__ unsigned g_wk16 [(size_t)LL * DD * KPD];
__device__ unsigned g_wv16 [(size_t)LL * DD * KPD];
__device__ unsigned g_wo16 [(size_t)LL * DD * KPD];
__device__ unsigned g_fc116[(size_t)LL * DFF * KPD];
__device__ unsigned g_fc216[(size_t)LL * DD * KPF];
__device__ unsigned g_wte16[(size_t)VV * KPD];

// ---------------- helpers ----------------
__device__ __forceinline__ uint32_t smem_u32(const void* p) {
    uint32_t a;
    asm("{ .reg .u64 t; cvta.to.shared.u64 t, %1; cvt.u32.u64 %0, t; }"
        : "=r"(a) : "l"(p));
    return a;
}
__device__ __forceinline__ void mma16(float* d, const unsigned* a, const unsigned* b) {
    asm volatile(
        "mma.sync.aligned.m16n8k16.row.col.f32.f16.f16.f32 "
        "{%0,%1,%2,%3},{%4,%5,%6,%7},{%8,%9},{%0,%1,%2,%3};"
        : "+f"(d[0]), "+f"(d[1]), "+f"(d[2]), "+f"(d[3])
        : "r"(a[0]), "r"(a[1]), "r"(a[2]), "r"(a[3]), "r"(b[0]), "r"(b[1]));
}
#define LDSM4(r0, r1, r2, r3, addr) \
    asm volatile("ldmatrix.sync.aligned.m8n8.x4.shared.b16 {%0,%1,%2,%3}, [%4];" \
                 : "=r"(r0), "=r"(r1), "=r"(r2), "=r"(r3) : "r"(addr))
__device__ __forceinline__ unsigned packh2(float lo, float hi) {
    __half2 h = __floats2half2_rn(lo, hi);
    return *reinterpret_cast<unsigned*>(&h);
}
__device__ __forceinline__ void cp16(uint32_t d, const void* g) {
    asm volatile("cp.async.cg.shared.global [%0], [%1], 16;" :: "r"(d), "l"(g));
}
__device__ __forceinline__ void cp16g(uint32_t d, const void* g, int sz) {
    asm volatile("cp.async.cg.shared.global [%0], [%1], 16, %2;"
                 :: "r"(d), "l"(g), "r"(sz));
}

// ---------------- weight packing (once per replay; vectorized) -------------
// W [L][K][N] f32 -> out [L][N][K/2] half2 (transpose via smem)
// float4 loads, uint2 stores. Bit-identical values to the scalar version.
__global__ void pack_t(const float* __restrict__ W, unsigned* __restrict__ out,
                       int K, int N)
{
    __shared__ float t[64][65];
    const int n0 = blockIdx.x * 64, k0 = blockIdx.y * 64, l = blockIdx.z;
    const float* Wl = W + (size_t)l * K * N;
    unsigned* ol = out + (size_t)l * N * (K >> 1);
    const int tid = threadIdx.x;
    #pragma unroll
    for (int p = 0; p < 4; p++) {
        int s  = tid + p * 256;          // 0..1023 float4 slots
        int kk = s >> 4, n4 = (s & 15) * 4;
        float4 v = *(const float4*)(Wl + (size_t)(k0 + kk) * N + n0 + n4);
        t[kk][n4]     = v.x;
        t[kk][n4 + 1] = v.y;
        t[kk][n4 + 2] = v.z;
        t[kk][n4 + 3] = v.w;
    }
    __syncthreads();
    #pragma unroll
    for (int p = 0; p < 4; p++) {
        int s   = tid + p * 256;         // 0..1023 uint2 slots
        int nn  = s >> 4, kp2 = (s & 15) * 2;    // kp2 even
        unsigned u0 = packh2(t[2 * kp2][nn],     t[2 * kp2 + 1][nn]);
        unsigned u1 = packh2(t[2 * kp2 + 2][nn], t[2 * kp2 + 3][nn]);
        *(uint2*)(ol + (size_t)(n0 + nn) * (K >> 1) + (k0 >> 1) + kp2) =
            make_uint2(u0, u1);
    }
}
// wte [V][768] f32 -> [V][384] half2; flat (768 % 4 == 0 so rows flatten exactly)
__global__ void pack_nk(const float* __restrict__ W, unsigned* __restrict__ out,
                        int total2)
{
    int i = blockIdx.x * 256 + threadIdx.x;      // uint2 index
    if (i >= total2) return;
    float4 f = *(const float4*)(W + (size_t)i * 4);
    *(uint2*)(out + (size_t)i * 2) = make_uint2(packh2(f.x, f.y), packh2(f.z, f.w));
}

// ---------------- fp16 NT GEMM: 8 warps, BK=64, 3-stage, templated M-tile --
// EPI: 0 none->f32, 1 +Cin->f32, 2 GELU->packed fp16,
//      3 QKV: z0->q16, z1->k16, z2->fused V transpose to vph/vpl (MT=128 only)
// NG: guard N (head gemm; N odd -> scalar stores only)
// MT: CTA M-tile rows (128 or 64); warp tile (MT/2)x32.
#define APAD 36

template<int EPI, bool NG, int MT>
__global__ __launch_bounds__(256, 2)
void mma_gemm(const unsigned* __restrict__ A,
              const unsigned* __restrict__ B0, const unsigned* __restrict__ B1,
              const unsigned* __restrict__ B2,
              const float* __restrict__ Cin, void* __restrict__ Cv,
              float* __restrict__ C1f,
              unsigned* __restrict__ Vh, unsigned* __restrict__ Vl,
              int N, int K)
{
    extern __shared__ unsigned gsm[];
    constexpr int AWRD = MT * APAD;            // A tile words
    constexpr int STGW = (MT + 128) * APAD;    // stage words
    constexpr int MTC  = MT / 32;              // mt count per warp

    const unsigned* B = (blockIdx.z == 0) ? B0 : ((blockIdx.z == 1) ? B1 : B2);
    float* Cf = (blockIdx.z == 0) ? (float*)Cv : C1f;
    unsigned* C16 = (unsigned*)Cv;

    const int tid  = threadIdx.x;
    const int lane = tid & 31;
    const int warp = tid >> 5;
    const int wm = warp >> 2, wn = warp & 3;       // 2 x 4
    const int lr = lane >> 2, lq = lane & 3;
    const int m0 = blockIdx.y * MT;
    const int n0 = blockIdx.x * 128;
    const int KA = K >> 1;

    const uint32_t sbase = smem_u32(gsm);
    const int lrow = lane & 7, lg = lane >> 3;
    const uint32_t aoff = (uint32_t)(((wm * (MT / 2) + (lg & 1) * 8 + lrow) * APAD
                                      + (lg >> 1) * 4) * 4);
    const uint32_t boff = (uint32_t)(((wn * 32 + (lg >> 1) * 8 + lrow) * APAD
                                      + (lg & 1) * 4) * 4);

    float acc[MTC][4][4];
    #pragma unroll
    for (int i = 0; i < MTC; i++)
        #pragma unroll
        for (int j = 0; j < 4; j++)
            #pragma unroll
            for (int t = 0; t < 4; t++) acc[i][j][t] = 0.0f;

    auto load_stage = [&](int stg) {
        const int slot = stg % 3;
        const uint32_t sa = sbase + (uint32_t)(slot * STGW) * 4u;
        const uint32_t sb = sa + (uint32_t)AWRD * 4u;
        const int kp0 = stg * 32;
        #pragma unroll
        for (int p = 0; p < MT / 32; p++) {        // A: MT*32 words
            int s = tid + p * 256;
            int r = s >> 3, c4 = (s & 7) * 4;
            cp16(sa + (uint32_t)(r * APAD + c4) * 4u,
                 A + (size_t)(m0 + r) * KA + kp0 + c4);
        }
        #pragma unroll
        for (int p = 0; p < 4; p++) {              // B: 128*32 words
            int s = tid + p * 256;
            int r = s >> 3, c4 = (s & 7) * 4;
            if (NG) {
                int n = n0 + r;
                int ok = (n < N);
                cp16g(sb + (uint32_t)(r * APAD + c4) * 4u,
                      B + (size_t)(ok ? n : 0) * KA + kp0 + c4, ok ? 16 : 0);
            } else {
                cp16(sb + (uint32_t)(r * APAD + c4) * 4u,
                     B + (size_t)(n0 + r) * KA + kp0 + c4);
            }
        }
        asm volatile("cp.async.commit_group;" ::: "memory");
    };

    auto compute = [&](int slot) {
        const uint32_t sa = sbase + (uint32_t)(slot * STGW) * 4u;
        const uint32_t sb = sa + (uint32_t)AWRD * 4u;
        #pragma unroll
        for (int kc = 0; kc < 4; kc++) {
            const uint32_t kbb = (uint32_t)(kc * 32);
            unsigned af[MTC][4];
            #pragma unroll
            for (int mt = 0; mt < MTC; mt++) {
                uint32_t addr = sa + aoff + kbb + (uint32_t)(mt * 16 * APAD * 4);
                LDSM4(af[mt][0], af[mt][1], af[mt][2], af[mt][3], addr);
            }
            unsigned bf[4][2];
            #pragma unroll
            for (int np = 0; np < 2; np++) {
                uint32_t addr = sb + boff + kbb + (uint32_t)(np * 16 * APAD * 4);
                unsigned r0, r1, r2, r3;
                LDSM4(r0, r1, r2, r3, addr);
                bf[np * 2][0] = r0;     bf[np * 2][1] = r1;
                bf[np * 2 + 1][0] = r2; bf[np * 2 + 1][1] = r3;
            }
            #pragma unroll
            for (int mt = 0; mt < MTC; mt++)
                #pragma unroll
                for (int nt = 0; nt < 4; nt++)
                    mma16(acc[mt][nt], af[mt], bf[nt]);
        }
    };

    const int nIter = K >> 6;
    load_stage(0);
    load_stage(1);
    for (int it = 0; it < nIter; it++) {
        if (it + 1 < nIter) asm volatile("cp.async.wait_group 1;" ::: "memory");
        else                asm volatile("cp.async.wait_group 0;" ::: "memory");
        __syncthreads();
        if (it + 2 < nIter) load_stage(it + 2);
        compute(it % 3);
    }

    // ---- fused V transpose epilogue (EPI==3, z==2; MT=128 only) ----
    if (EPI == 3 && MT == 128) {
        if (blockIdx.z == 2) {
            float* st = (float*)gsm;           // [128][129] f32
            __syncthreads();
            #pragma unroll
            for (int mt = 0; mt < MTC; mt++) {
                int r = wm * (MT / 2) + mt * 16 + lr;
                #pragma unroll
                for (int nt = 0; nt < 4; nt++) {
                    int c = wn * 32 + nt * 8 + lq * 2;
                    float* a4 = acc[mt][nt];
                    st[r * 129 + c]           = a4[0];
                    st[r * 129 + c + 1]       = a4[1];
                    st[(r + 8) * 129 + c]     = a4[2];
                    st[(r + 8) * 129 + c + 1] = a4[3];
                }
            }
            __syncthreads();
            const int b  = m0 / SS;
            const int j0 = m0 & (SS - 1);
            #pragma unroll
            for (int p = 0; p < 32; p++) {
                int idx = tid + p * 256;
                int cc = idx >> 6, jp = idx & 63;
                float v0 = st[(2 * jp) * 129 + cc];
                float v1 = st[(2 * jp + 1) * 129 + cc];
                unsigned hi = packh2(v0, v1);
                __half2 hh = *reinterpret_cast<__half2*>(&hi);
                float2 fh = __half22float2(hh);
                unsigned lo = packh2(v0 - fh.x, v1 - fh.y);
                int h  = (n0 + cc) >> 6;
                int dk = (n0 + cc) & 63;
                size_t o = ((size_t)(b * HH + h) * DKK + dk) * (SS / 2)
                           + (j0 >> 1) + jp;
                Vh[o] = hi;
                Vl[o] = lo;
            }
            return;
        }
    }

    // ---- standard epilogues ----
    #pragma unroll
    for (int mt = 0; mt < MTC; mt++) {
        int r0 = m0 + wm * (MT / 2) + mt * 16 + lr;
        #pragma unroll
        for (int nt = 0; nt < 4; nt++) {
            int col = n0 + wn * 32 + nt * 8 + lq * 2;
            float* a4 = acc[mt][nt];
            float v00 = a4[0], v01 = a4[1], v10 = a4[2], v11 = a4[3];
            if (EPI == 2) {
                v00 = 0.5f * v00 * (1.0f + erff(v00 * 0.70710678118654752f));
                v01 = 0.5f * v01 * (1.0f + erff(v01 * 0.70710678118654752f));
                v10 = 0.5f * v10 * (1.0f + erff(v10 * 0.70710678118654752f));
                v11 = 0.5f * v11 * (1.0f + erff(v11 * 0.70710678118654752f));
                int nw = N >> 1;
                C16[(size_t)r0 * nw + (col >> 1)]       = packh2(v00, v01);
                C16[(size_t)(r0 + 8) * nw + (col >> 1)] = packh2(v10, v11);
            } else if (EPI == 3) {
                unsigned* o = (blockIdx.z == 0) ? (unsigned*)Cv : (unsigned*)C1f;
                int nw = N >> 1;
                o[(size_t)r0 * nw + (col >> 1)]       = packh2(v00, v01);
                o[(size_t)(r0 + 8) * nw + (col >> 1)] = packh2(v10, v11);
            } else {
                size_t o0 = (size_t)r0 * N + col;
                size_t o1 = (size_t)(r0 + 8) * N + col;
                if (EPI == 1) {
                    float2 c0 = *(const float2*)(Cin + o0);
                    float2 c1 = *(const float2*)(Cin + o1);
                    v00 += c0.x; v01 += c0.y; v10 += c1.x; v11 += c1.y;
                }
                if (!NG) {
                    *(float2*)(Cf + o0) = make_float2(v00, v01);
                    *(float2*)(Cf + o1) = make_float2(v10, v11);
                } else {
                    // N odd (head gemm): scalar stores only.
                    if (col < N)     { Cf[o0] = v00;     Cf[o1] = v10; }
                    if (col + 1 < N) { Cf[o0 + 1] = v01; Cf[o1 + 1] = v11; }
                }
            }
        }
    }
}

// ---------------- embedding ----------------
__global__ void embed_kernel(const int* __restrict__ idx,
                             const float* __restrict__ wte,
                             const float* __restrict__ wpe,
                             float* __restrict__ x)
{
    int row = blockIdx.x;
    int s   = row & (SS - 1);
    int tok = idx[row];
    int tid = threadIdx.x;
    #pragma unroll
    for (int l = 0; l < 3; l++) {
        int d = tid + l * 256;
        x[(size_t)row * DD + d] = wte[(size_t)tok * DD + d] + wpe[(size_t)s * DD + d];
    }
}

// ---------------- layernorm -> packed fp16 (shuffle reductions) ------------
__global__ void layernorm_kernel(const float* __restrict__ x,
                                 const float* __restrict__ w,
                                 const float* __restrict__ b,
                                 unsigned* __restrict__ y16)
{
    int row = blockIdx.x;
    const float2* p2 = (const float2*)(x + (size_t)row * DD);
    int tid = threadIdx.x;                 // 256
    int lane = tid & 31, wid = tid >> 5;
    float2 f1 = p2[tid];
    float2 f2 = (tid < 128) ? p2[tid + 256] : make_float2(0.f, 0.f);

    __shared__ float ws[8], ws2[8];
    float s = f1.x + f1.y + f2.x + f2.y;
    #pragma unroll
    for (int o = 16; o > 0; o >>= 1) s += __shfl_xor_sync(0xffffffffu, s, o);
    if (lane == 0) ws[wid] = s;
    __syncthreads();
    float mean = (ws[0] + ws[1] + ws[2] + ws[3] + ws[4] + ws[5] + ws[6] + ws[7])
                 * (1.0f / DD);

    float a0 = f1.x - mean, a1 = f1.y - mean;
    float a2 = f2.x - mean, a3 = f2.y - mean;
    float sq = a0 * a0 + a1 * a1 + ((tid < 128) ? (a2 * a2 + a3 * a3) : 0.f);
    #pragma unroll
    for (int o = 16; o > 0; o >>= 1) sq += __shfl_xor_sync(0xffffffffu, sq, o);
    if (lane == 0) ws2[wid] = sq;
    __syncthreads();
    float var = (ws2[0] + ws2[1] + ws2[2] + ws2[3] + ws2[4] + ws2[5] + ws2[6] + ws2[7])
                * (1.0f / DD);
    float rstd = rsqrtf(var + 1e-5f);

    const float2* w2 = (const float2*)w;
    const float2* b2 = (const float2*)b;
    unsigned* yr = y16 + (size_t)row * KPD;
    {
        float2 ww = w2[tid], bb = b2[tid];
        yr[tid] = packh2(a0 * rstd * ww.x + bb.x, a1 * rstd * ww.y + bb.y);
    }
    if (tid < 128) {
        float2 ww = w2[tid + 256], bb = b2[tid + 256];
        yr[tid + 256] = packh2(a2 * rstd * ww.x + bb.x, a3 * rstd * ww.y + bb.y);
    }
}

// ---------------- fused flash attention (fp16, double-buffered KV) ---------
#define FST 36
#define FQW (64 * FST)
#define FBW (3 * 64 * FST)
#define FA_SMEM_BYTES ((FQW + 2 * FBW) * 4)   // 64512

__global__ __launch_bounds__(128, 3)
void flash_attn_kernel(const unsigned* __restrict__ q16,
                       const unsigned* __restrict__ k16,
                       const unsigned* __restrict__ vph,
                       const unsigned* __restrict__ vpl,
                       unsigned* __restrict__ O16)
{
    extern __shared__ unsigned fsm[];

    const int tid  = threadIdx.x;
    const int lane = tid & 31;
    const int w    = tid >> 5;
    const int lr   = lane >> 2;
    const int lq   = lane & 3;
    const int it   = (SS / 64 - 1) - blockIdx.x;
    const int bh   = blockIdx.y;
    const int b    = bh / HH, h = bh % HH;
    const int i0   = it * 64;
    const int lrow = lane & 7, lg = lane >> 3;

    const uint32_t sQb = smem_u32(fsm);
    const uint32_t aoff = (uint32_t)(((w * 16 + (lg & 1) * 8 + lrow) * FST
                                      + (lg >> 1) * 4) * 4);
    const uint32_t boff = (uint32_t)((((lg >> 1) * 8 + lrow) * FST
                                      + (lg & 1) * 4) * 4);

    auto load_tile = [&](int j0, int buf) {
        const uint32_t kb  = sQb + (uint32_t)(FQW + buf * FBW) * 4u;
        const uint32_t vhb = kb + (uint32_t)(64 * FST) * 4u;
        const uint32_t vlb = vhb + (uint32_t)(64 * FST) * 4u;
        #pragma unroll
        for (int p = 0; p < 4; p++) {
            int s = tid + p * 128;
            int r = s >> 3, c4 = (s & 7) * 4;
            cp16(kb + (uint32_t)(r * FST + c4) * 4u,
                 k16 + (size_t)(b * SS + j0 + r) * KPD + h * 32 + c4);
            size_t vo = ((size_t)bh * DKK + r) * (SS / 2) + (j0 >> 1) + c4;
            cp16(vhb + (uint32_t)(r * FST + c4) * 4u, vph + vo);
            cp16(vlb + (uint32_t)(r * FST + c4) * 4u, vpl + vo);
        }
        asm volatile("cp.async.commit_group;" ::: "memory");
    };

    #pragma unroll
    for (int p = 0; p < 4; p++) {
        int s = tid + p * 128;
        int r = s >> 3, c4 = (s & 7) * 4;
        cp16(sQb + (uint32_t)(r * FST + c4) * 4u,
             q16 + (size_t)(b * SS + i0 + r) * KPD + h * 32 + c4);
    }
    asm volatile("cp.async.commit_group;" ::: "memory");
    load_tile(0, 0);
    asm volatile("cp.async.wait_group 1;" ::: "memory");
    __syncthreads();

    unsigned qf[4][4];
    #pragma unroll
    for (int kc = 0; kc < 4; kc++)
        LDSM4(qf[kc][0], qf[kc][1], qf[kc][2], qf[kc][3], sQb + aoff + kc * 32);

    float oacc[8][4];
    #pragma unroll
    for (int nt = 0; nt < 8; nt++)
        #pragma unroll
        for (int e = 0; e < 4; e++) oacc[nt][e] = 0.0f;
    float m0 = -1e30f, m1 = -1e30f, l0 = 0.0f, l1 = 0.0f;

    int buf = 0;
    for (int j0 = 0; j0 <= i0; j0 += 64) {
        __syncthreads();
        const bool more = (j0 + 64 <= i0);
        if (more) load_tile(j0 + 64, buf ^ 1);
        if (more) asm volatile("cp.async.wait_group 1;" ::: "memory");
        else      asm volatile("cp.async.wait_group 0;" ::: "memory");
        __syncthreads();

        const uint32_t kb  = sQb + (uint32_t)(FQW + buf * FBW) * 4u;
        const uint32_t vhb = kb + (uint32_t)(64 * FST) * 4u;
        const uint32_t vlb = vhb + (uint32_t)(64 * FST) * 4u;

        float sacc[8][4];
        #pragma unroll
        for (int nt = 0; nt < 8; nt++)
            #pragma unroll
            for (int e = 0; e < 4; e++) sacc[nt][e] = 0.0f;
        #pragma unroll
        for (int kc = 0; kc < 4; kc++) {
            #pragma unroll
            for (int nb = 0; nb < 4; nb++) {
                unsigned r0, r1, r2, r3;
                LDSM4(r0, r1, r2, r3,
                      kb + boff + (uint32_t)(nb * 16 * FST * 4) + kc * 32);
                unsigned b0[2] = {r0, r1}, b1[2] = {r2, r3};
                mma16(sacc[nb * 2],     qf[kc], b0);
                mma16(sacc[nb * 2 + 1], qf[kc], b1);
            }
        }

        #pragma unroll
        for (int nt = 0; nt < 8; nt++)
            #pragma unroll
            for (int e = 0; e < 4; e++) sacc[nt][e] *= 0.125f;
        if (j0 == i0) {
            int ii0 = w * 16 + lr, ii1 = ii0 + 8;
            #pragma unroll
            for (int nt = 0; nt < 8; nt++) {
                int jj = nt * 8 + 2 * lq;
                if (jj     > ii0) sacc[nt][0] = -1e30f;
                if (jj + 1 > ii0) sacc[nt][1] = -1e30f;
                if (jj     > ii1) sacc[nt][2] = -1e30f;
                if (jj + 1 > ii1) sacc[nt][3] = -1e30f;
            }
        }

        float rm0 = -1e30f, rm1 = -1e30f;
        #pragma unroll
        for (int nt = 0; nt < 8; nt++) {
            rm0 = fmaxf(rm0, fmaxf(sacc[nt][0], sacc[nt][1]));
            rm1 = fmaxf(rm1, fmaxf(sacc[nt][2], sacc[nt][3]));
        }
        rm0 = fmaxf(rm0, __shfl_xor_sync(0xffffffffu, rm0, 1));
        rm0 = fmaxf(rm0, __shfl_xor_sync(0xffffffffu, rm0, 2));
        rm1 = fmaxf(rm1, __shfl_xor_sync(0xffffffffu, rm1, 1));
        rm1 = fmaxf(rm1, __shfl_xor_sync(0xffffffffu, rm1, 2));
        float mn0 = fmaxf(m0, rm0), mn1 = fmaxf(m1, rm1);
        float f0 = __expf(m0 - mn0), f1 = __expf(m1 - mn1);
        float ps0 = 0.0f, ps1 = 0.0f;
        #pragma unroll
        for (int nt = 0; nt < 8; nt++) {
            float p0 = __expf(sacc[nt][0] - mn0); sacc[nt][0] = p0; ps0 += p0;
            float p1 = __expf(sacc[nt][1] - mn0); sacc[nt][1] = p1; ps0 += p1;
            float p2 = __expf(sacc[nt][2] - mn1); sacc[nt][2] = p2; ps1 += p2;
            float p3 = __expf(sacc[nt][3] - mn1); sacc[nt][3] = p3; ps1 += p3;
        }
        ps0 += __shfl_xor_sync(0xffffffffu, ps0, 1);
        ps0 += __shfl_xor_sync(0xffffffffu, ps0, 2);
        ps1 += __shfl_xor_sync(0xffffffffu, ps1, 1);
        ps1 += __shfl_xor_sync(0xffffffffu, ps1, 2);
        l0 = l0 * f0 + ps0;
        l1 = l1 * f1 + ps1;
        m0 = mn0; m1 = mn1;
        #pragma unroll
        for (int nt = 0; nt < 8; nt++) {
            oacc[nt][0] *= f0; oacc[nt][1] *= f0;
            oacc[nt][2] *= f1; oacc[nt][3] *= f1;
        }

        #pragma unroll
        for (int kc = 0; kc < 4; kc++) {
            unsigned ah[4], al[4];
            #pragma unroll
            for (int hsel = 0; hsel < 2; hsel++) {
                const float* s0 = sacc[2 * kc + hsel];
                unsigned hi0 = packh2(s0[0], s0[1]);
                unsigned hi1 = packh2(s0[2], s0[3]);
                __half2 h2a = *reinterpret_cast<__half2*>(&hi0);
                __half2 h2b = *reinterpret_cast<__half2*>(&hi1);
                float2 fa = __half22float2(h2a);
                float2 fb = __half22float2(h2b);
                ah[hsel * 2]     = hi0;
                ah[hsel * 2 + 1] = hi1;
                al[hsel * 2]     = packh2(s0[0] - fa.x, s0[1] - fa.y);
                al[hsel * 2 + 1] = packh2(s0[2] - fb.x, s0[3] - fb.y);
            }
            #pragma unroll
            for (int nb = 0; nb < 4; nb++) {
                uint32_t va = boff + (uint32_t)(nb * 16 * FST * 4) + kc * 32;
                unsigned h0, h1, h2, h3, g0, g1, g2, g3;
                LDSM4(h0, h1, h2, h3, vhb + va);
                LDSM4(g0, g1, g2, g3, vlb + va);
                unsigned bh0[2] = {h0, h1}, bh1[2] = {h2, h3};
                unsigned bl0[2] = {g0, g1}, bl1[2] = {g2, g3};
                mma16(oacc[nb * 2],     ah, bh0);
                mma16(oacc[nb * 2],     al, bh0);
                mma16(oacc[nb * 2],     ah, bl0);
                mma16(oacc[nb * 2 + 1], ah, bh1);
                mma16(oacc[nb * 2 + 1], al, bh1);
                mma16(oacc[nb * 2 + 1], ah, bl1);
            }
        }
        buf ^= 1;
    }

    float inv0 = 1.0f / l0, inv1 = 1.0f / l1;
    int row0 = b * SS + i0 + w * 16 + lr;
    unsigned* Ob = O16 + (size_t)row0 * KPD + h * 32;
    #pragma unroll
    for (int nt = 0; nt < 8; nt++) {
        Ob[nt * 4 + lq] = packh2(oacc[nt][0] * inv0, oacc[nt][1] * inv0);
        Ob[(size_t)8 * KPD + nt * 4 + lq] = packh2(oacc[nt][2] * inv1, oacc[nt][3] * inv1);
    }
}

// ---------------- host launcher ----------------
extern "C" void kernel_launch(void* const* d_in, const int* in_sizes, int n_in,
                              void* d_out, int out_size)
{
    const int*   idx   = (const int*)  d_in[0];
    const float* wte   = (const float*)d_in[1];
    const float* wpe   = (const float*)d_in[2];
    const float* ln1_w = (const float*)d_in[3];
    const float* ln1_b = (const float*)d_in[4];
    const float* wq    = (const float*)d_in[5];
    const float* wk    = (const float*)d_in[6];
    const float* wv    = (const float*)d_in[7];
    const float* wo    = (const float*)d_in[8];
    const float* ln2_w = (const float*)d_in[9];
    const float* ln2_b = (const float*)d_in[10];
    const float* fc1   = (const float*)d_in[11];
    const float* fc2   = (const float*)d_in[12];
    const float* lnf_w = (const float*)d_in[13];
    const float* lnf_b = (const float*)d_in[14];
    float* out = (float*)d_out;

    float *x;
    unsigned *q16, *k16, *h16, *tmp16, *ff16, *vph, *vpl;
    unsigned *wq16, *wk16, *wv16, *wo16, *fc116, *fc216, *wte16;
    cudaGetSymbolAddress((void**)&x,     g_x);
    cudaGetSymbolAddress((void**)&q16,   g_q16);
    cudaGetSymbolAddress((void**)&k16,   g_k16);
    cudaGetSymbolAddress((void**)&h16,   g_h16);
    cudaGetSymbolAddress((void**)&tmp16, g_tmp16);
    cudaGetSymbolAddress((void**)&ff16,  g_ff16);
    cudaGetSymbolAddress((void**)&vph,   g_vph);
    cudaGetSymbolAddress((void**)&vpl,   g_vpl);
    cudaGetSymbolAddress((void**)&wq16,  g_wq16);
    cudaGetSymbolAddress((void**)&wk16,  g_wk16);
    cudaGetSymbolAddress((void**)&wv16,  g_wv16);
    cudaGetSymbolAddress((void**)&wo16,  g_wo16);
    cudaGetSymbolAddress((void**)&fc116, g_fc116);
    cudaGetSymbolAddress((void**)&fc216, g_fc216);
    cudaGetSymbolAddress((void**)&wte16, g_wte16);

    const int gs128 = 3 * (256 * APAD) * 4;    // 110592 bytes
    const int gs64  = 3 * (192 * APAD) * 4;    // 82944 bytes
    cudaFuncSetAttribute(mma_gemm<1,false,128>, cudaFuncAttributeMaxDynamicSharedMemorySize, gs128);
    cudaFuncSetAttribute(mma_gemm<2,false,128>, cudaFuncAttributeMaxDynamicSharedMemorySize, gs128);
    cudaFuncSetAttribute(mma_gemm<3,false,128>, cudaFuncAttributeMaxDynamicSharedMemorySize, gs128);
    cudaFuncSetAttribute(mma_gemm<0,true,128>,  cudaFuncAttributeMaxDynamicSharedMemorySize, gs128);
    cudaFuncSetAttribute(mma_gemm<1,false,64>,  cudaFuncAttributeMaxDynamicSharedMemorySize, gs64);
    cudaFuncSetAttribute(flash_attn_kernel,
                         cudaFuncAttributeMaxDynamicSharedMemorySize, FA_SMEM_BYTES);

    pack_t<<<dim3(DD / 64, DD / 64, LL), 256>>>(wq, wq16, DD, DD);
    pack_t<<<dim3(DD / 64, DD / 64, LL), 256>>>(wk, wk16, DD, DD);
    pack_t<<<dim3(DD / 64, DD / 64, LL), 256>>>(wv, wv16, DD, DD);
    pack_t<<<dim3(DD / 64, DD / 64, LL), 256>>>(wo, wo16, DD, DD);
    pack_t<<<dim3(DFF / 64, DD / 64, LL), 256>>>(fc1, fc116, DD, DFF);
    pack_t<<<dim3(DD / 64, DFF / 64, LL), 256>>>(fc2, fc216, DFF, DD);
    {
        int t2 = VV * KPD / 2;                  // uint2 count
        pack_nk<<<(t2 + 255) / 256, 256>>>(wte, wte16, t2);
    }

    embed_kernel<<<NTOK, 256>>>(idx, wte, wpe, x);

    dim3 gQKV(DD / 128, NTOK / 128, 3);
    dim3 gD64(DD / 128, NTOK / 64, 1);      // (6, 64) for wo / fc2
    dim3 gF  (DFF / 128, NTOK / 128, 1);

    for (int l = 0; l < LL; l++) {
        unsigned* Wq = wq16 + (size_t)l * DD * KPD;
        unsigned* Wk = wk16 + (size_t)l * DD * KPD;
        unsigned* Wv = wv16 + (size_t)l * DD * KPD;
        unsigned* Wo = wo16 + (size_t)l * DD * KPD;
        unsigned* W1 = fc116 + (size_t)l * DFF * KPD;
        unsigned* W2 = fc216 + (size_t)l * DD * KPF;

        layernorm_kernel<<<NTOK, 256>>>(x, ln1_w + l * DD, ln1_b + l * DD, h16);

        // q -> q16, k -> k16, v -> fused transpose into vph/vpl
        mma_gemm<3,false,128><<<gQKV, 256, gs128>>>(h16, Wq, Wk, Wv, nullptr,
                                                    q16, (float*)k16, vph, vpl,
                                                    DD, DD);

        flash_attn_kernel<<<dim3(SS / 64, BB * HH), 128, FA_SMEM_BYTES>>>(
            q16, k16, vph, vpl, tmp16);

        mma_gemm<1,false,64><<<gD64, 256, gs64>>>(tmp16, Wo, Wo, Wo, x, x,
                                                  nullptr, nullptr, nullptr,
                                                  DD, DD);

        layernorm_kernel<<<NTOK, 256>>>(x, ln2_w + l * DD, ln2_b + l * DD, h16);
        mma_gemm<2,false,128><<<gF, 256, gs128>>>(h16, W1, W1, W1, nullptr, ff16,
                                                  nullptr, nullptr, nullptr,
                                                  DFF, DD);
        mma_gemm<1,false,64><<<gD64, 256, gs64>>>(ff16, W2, W2, W2, x, x,
                                                  nullptr, nullptr, nullptr,
                                                  DD, DFF);
    }

    layernorm_kernel<<<NTOK, 256>>>(x, lnf_w, lnf_b, h16);
    mma_gemm<0,true,128><<<dim3((VV + 127) / 128, NTOK / 128, 1), 256, gs128>>>(
        h16, wte16, wte16, wte16, nullptr, out, nullptr, nullptr, nullptr, VV, DD);
}

// round 17
// speedup vs baseline: 1.0657x; 1.0046x over previous
#include <cuda_runtime.h>
#include <cuda_bf16.h>
#include <cuda_fp16.h>
#include <math.h>
#include <stdint.h>

// ---------------- problem constants ----------------
#define BB 4
#define SS 1024
#define LL 12
#define DD 768
#define HH 12
#define DKK 64
#define DFF 3072
#define VV 50257
#define NTOK (BB*SS)          // 4096
#define KPD (DD/2)            // 384
#define KPF (DFF/2)           // 1536

// ---------------- scratch (device globals; no allocs allowed) --------------
__device__ unsigned g_q16 [(size_t)NTOK * KPD];
__device__ unsigned g_k16 [(size_t)NTOK * KPD];
__device__ unsigned g_h16 [(size_t)NTOK * KPD];
__device__ unsigned g_tmp16[(size_t)NTOK * KPD];
__device__ unsigned g_ff16 [(size_t)NTOK * KPF];
__device__ float    g_x   [(size_t)NTOK * DD];
__device__ unsigned g_vph [(size_t)BB * HH * DKK * (SS/2)];
__device__ unsigned g_vpl [(size_t)BB * HH * DKK * (SS/2)];
// packed fp16 weights, K-major: [L][N][K/2] half2 words
__device__ unsigned g_wq16 [(size_t)LL * DD * KPD];
__device__ unsigned g_wk16 [(size_t)LL * DD * KPD];
__device__ unsigned g_wv16 [(size_t)LL * DD * KPD];
__device__ unsigned g_wo16 [(size_t)LL * DD * KPD];
__device__ unsigned g_fc116[(size_t)LL * DFF * KPD];
__device__ unsigned g_fc216[(size_t)LL * DD * KPF];
__device__ unsigned g_wte16[(size_t)VV * KPD];

// ---------------- helpers ----------------
__device__ __forceinline__ uint32_t smem_u32(const void* p) {
    uint32_t a;
    asm("{ .reg .u64 t; cvta.to.shared.u64 t, %1; cvt.u32.u64 %0, t; }"
        : "=r"(a) : "l"(p));
    return a;
}
__device__ __forceinline__ void mma16(float* d, const unsigned* a, const unsigned* b) {
    asm volatile(
        "mma.sync.aligned.m16n8k16.row.col.f32.f16.f16.f32 "
        "{%0,%1,%2,%3},{%4,%5,%6,%7},{%8,%9},{%0,%1,%2,%3};"
        : "+f"(d[0]), "+f"(d[1]), "+f"(d[2]), "+f"(d[3])
        : "r"(a[0]), "r"(a[1]), "r"(a[2]), "r"(a[3]), "r"(b[0]), "r"(b[1]));
}
#define LDSM4(r0, r1, r2, r3, addr) \
    asm volatile("ldmatrix.sync.aligned.m8n8.x4.shared.b16 {%0,%1,%2,%3}, [%4];" \
                 : "=r"(r0), "=r"(r1), "=r"(r2), "=r"(r3) : "r"(addr))
__device__ __forceinline__ unsigned packh2(float lo, float hi) {
    __half2 h = __floats2half2_rn(lo, hi);
    return *reinterpret_cast<unsigned*>(&h);
}
__device__ __forceinline__ void cp16(uint32_t d, const void* g) {
    asm volatile("cp.async.cg.shared.global [%0], [%1], 16;" :: "r"(d), "l"(g));
}
__device__ __forceinline__ void cp16g(uint32_t d, const void* g, int sz) {
    asm volatile("cp.async.cg.shared.global [%0], [%1], 16, %2;"
                 :: "r"(d), "l"(g), "r"(sz));
}

// ---------------- weight packing (once per replay; vectorized) -------------
__global__ void pack_t(const float* __restrict__ W, unsigned* __restrict__ out,
                       int K, int N)
{
    __shared__ float t[64][65];
    const int n0 = blockIdx.x * 64, k0 = blockIdx.y * 64, l = blockIdx.z;
    const float* Wl = W + (size_t)l * K * N;
    unsigned* ol = out + (size_t)l * N * (K >> 1);
    const int tid = threadIdx.x;
    #pragma unroll
    for (int p = 0; p < 4; p++) {
        int s  = tid + p * 256;
        int kk = s >> 4, n4 = (s & 15) * 4;
        float4 v = *(const float4*)(Wl + (size_t)(k0 + kk) * N + n0 + n4);
        t[kk][n4]     = v.x;
        t[kk][n4 + 1] = v.y;
        t[kk][n4 + 2] = v.z;
        t[kk][n4 + 3] = v.w;
    }
    __syncthreads();
    #pragma unroll
    for (int p = 0; p < 4; p++) {
        int s   = tid + p * 256;
        int nn  = s >> 4, kp2 = (s & 15) * 2;
        unsigned u0 = packh2(t[2 * kp2][nn],     t[2 * kp2 + 1][nn]);
        unsigned u1 = packh2(t[2 * kp2 + 2][nn], t[2 * kp2 + 3][nn]);
        *(uint2*)(ol + (size_t)(n0 + nn) * (K >> 1) + (k0 >> 1) + kp2) =
            make_uint2(u0, u1);
    }
}
__global__ void pack_nk(const float* __restrict__ W, unsigned* __restrict__ out,
                        int total2)
{
    int i = blockIdx.x * 256 + threadIdx.x;
    if (i >= total2) return;
    float4 f = *(const float4*)(W + (size_t)i * 4);
    *(uint2*)(out + (size_t)i * 2) = make_uint2(packh2(f.x, f.y), packh2(f.z, f.w));
}

// ---------------- fp16 NT GEMM: 8 warps, BK=64, 3-stage, templated M-tile --
// EPI: 0 none->f32, 1 +Cin->f32, 2 GELU->packed fp16,
//      3 QKV: z0->q16, z1->k16, z2->fused V transpose to vph/vpl (MT=128 only)
// NG: guard N (head gemm; N odd -> scalar stores only)
// MT: CTA M-tile rows (128 or 64); warp tile (MT/2)x32.
// SW: swap grid axes (m from blockIdx.x) for L2 B-tile reuse on huge-N gemms.
#define APAD 36

template<int EPI, bool NG, int MT, bool SW>
__global__ __launch_bounds__(256, 2)
void mma_gemm(const unsigned* __restrict__ A,
              const unsigned* __restrict__ B0, const unsigned* __restrict__ B1,
              const unsigned* __restrict__ B2,
              const float* __restrict__ Cin, void* __restrict__ Cv,
              float* __restrict__ C1f,
              unsigned* __restrict__ Vh, unsigned* __restrict__ Vl,
              int N, int K)
{
    extern __shared__ unsigned gsm[];
    constexpr int AWRD = MT * APAD;            // A tile words
    constexpr int STGW = (MT + 128) * APAD;    // stage words
    constexpr int MTC  = MT / 32;              // mt count per warp

    const unsigned* B = (blockIdx.z == 0) ? B0 : ((blockIdx.z == 1) ? B1 : B2);
    float* Cf = (blockIdx.z == 0) ? (float*)Cv : C1f;
    unsigned* C16 = (unsigned*)Cv;

    const int tid  = threadIdx.x;
    const int lane = tid & 31;
    const int warp = tid >> 5;
    const int wm = warp >> 2, wn = warp & 3;       // 2 x 4
    const int lr = lane >> 2, lq = lane & 3;
    const int m0 = (SW ? blockIdx.x : blockIdx.y) * MT;
    const int n0 = (SW ? blockIdx.y : blockIdx.x) * 128;
    const int KA = K >> 1;

    const uint32_t sbase = smem_u32(gsm);
    const int lrow = lane & 7, lg = lane >> 3;
    const uint32_t aoff = (uint32_t)(((wm * (MT / 2) + (lg & 1) * 8 + lrow) * APAD
                                      + (lg >> 1) * 4) * 4);
    const uint32_t boff = (uint32_t)(((wn * 32 + (lg >> 1) * 8 + lrow) * APAD
                                      + (lg & 1) * 4) * 4);

    float acc[MTC][4][4];
    #pragma unroll
    for (int i = 0; i < MTC; i++)
        #pragma unroll
        for (int j = 0; j < 4; j++)
            #pragma unroll
            for (int t = 0; t < 4; t++) acc[i][j][t] = 0.0f;

    auto load_stage = [&](int stg) {
        const int slot = stg % 3;
        const uint32_t sa = sbase + (uint32_t)(slot * STGW) * 4u;
        const uint32_t sb = sa + (uint32_t)AWRD * 4u;
        const int kp0 = stg * 32;
        #pragma unroll
        for (int p = 0; p < MT / 32; p++) {        // A: MT*32 words
            int s = tid + p * 256;
            int r = s >> 3, c4 = (s & 7) * 4;
            cp16(sa + (uint32_t)(r * APAD + c4) * 4u,
                 A + (size_t)(m0 + r) * KA + kp0 + c4);
        }
        #pragma unroll
        for (int p = 0; p < 4; p++) {              // B: 128*32 words
            int s = tid + p * 256;
            int r = s >> 3, c4 = (s & 7) * 4;
            if (NG) {
                int n = n0 + r;
                int ok = (n < N);
                cp16g(sb + (uint32_t)(r * APAD + c4) * 4u,
                      B + (size_t)(ok ? n : 0) * KA + kp0 + c4, ok ? 16 : 0);
            } else {
                cp16(sb + (uint32_t)(r * APAD + c4) * 4u,
                     B + (size_t)(n0 + r) * KA + kp0 + c4);
            }
        }
        asm volatile("cp.async.commit_group;" ::: "memory");
    };

    auto compute = [&](int slot) {
        const uint32_t sa = sbase + (uint32_t)(slot * STGW) * 4u;
        const uint32_t sb = sa + (uint32_t)AWRD * 4u;
        #pragma unroll
        for (int kc = 0; kc < 4; kc++) {
            const uint32_t kbb = (uint32_t)(kc * 32);
            unsigned af[MTC][4];
            #pragma unroll
            for (int mt = 0; mt < MTC; mt++) {
                uint32_t addr = sa + aoff + kbb + (uint32_t)(mt * 16 * APAD * 4);
                LDSM4(af[mt][0], af[mt][1], af[mt][2], af[mt][3], addr);
            }
            unsigned bf[4][2];
            #pragma unroll
            for (int np = 0; np < 2; np++) {
                uint32_t addr = sb + boff + kbb + (uint32_t)(np * 16 * APAD * 4);
                unsigned r0, r1, r2, r3;
                LDSM4(r0, r1, r2, r3, addr);
                bf[np * 2][0] = r0;     bf[np * 2][1] = r1;
                bf[np * 2 + 1][0] = r2; bf[np * 2 + 1][1] = r3;
            }
            #pragma unroll
            for (int mt = 0; mt < MTC; mt++)
                #pragma unroll
                for (int nt = 0; nt < 4; nt++)
                    mma16(acc[mt][nt], af[mt], bf[nt]);
        }
    };

    const int nIter = K >> 6;
    load_stage(0);
    load_stage(1);
    for (int it = 0; it < nIter; it++) {
        if (it + 1 < nIter) asm volatile("cp.async.wait_group 1;" ::: "memory");
        else                asm volatile("cp.async.wait_group 0;" ::: "memory");
        __syncthreads();
        if (it + 2 < nIter) load_stage(it + 2);
        compute(it % 3);
    }

    // ---- fused V transpose epilogue (EPI==3, z==2; MT=128 only) ----
    if (EPI == 3 && MT == 128) {
        if (blockIdx.z == 2) {
            float* st = (float*)gsm;           // [128][129] f32
            __syncthreads();
            #pragma unroll
            for (int mt = 0; mt < MTC; mt++) {
                int r = wm * (MT / 2) + mt * 16 + lr;
                #pragma unroll
                for (int nt = 0; nt < 4; nt++) {
                    int c = wn * 32 + nt * 8 + lq * 2;
                    float* a4 = acc[mt][nt];
                    st[r * 129 + c]           = a4[0];
                    st[r * 129 + c + 1]       = a4[1];
                    st[(r + 8) * 129 + c]     = a4[2];
                    st[(r + 8) * 129 + c + 1] = a4[3];
                }
            }
            __syncthreads();
            const int b  = m0 / SS;
            const int j0 = m0 & (SS - 1);
            #pragma unroll
            for (int p = 0; p < 32; p++) {
                int idx = tid + p * 256;
                int cc = idx >> 6, jp = idx & 63;
                float v0 = st[(2 * jp) * 129 + cc];
                float v1 = st[(2 * jp + 1) * 129 + cc];
                unsigned hi = packh2(v0, v1);
                __half2 hh = *reinterpret_cast<__half2*>(&hi);
                float2 fh = __half22float2(hh);
                unsigned lo = packh2(v0 - fh.x, v1 - fh.y);
                int h  = (n0 + cc) >> 6;
                int dk = (n0 + cc) & 63;
                size_t o = ((size_t)(b * HH + h) * DKK + dk) * (SS / 2)
                           + (j0 >> 1) + jp;
                Vh[o] = hi;
                Vl[o] = lo;
            }
            return;
        }
    }

    // ---- standard epilogues ----
    #pragma unroll
    for (int mt = 0; mt < MTC; mt++) {
        int r0 = m0 + wm * (MT / 2) + mt * 16 + lr;
        #pragma unroll
        for (int nt = 0; nt < 4; nt++) {
            int col = n0 + wn * 32 + nt * 8 + lq * 2;
            float* a4 = acc[mt][nt];
            float v00 = a4[0], v01 = a4[1], v10 = a4[2], v11 = a4[3];
            if (EPI == 2) {
                v00 = 0.5f * v00 * (1.0f + erff(v00 * 0.70710678118654752f));
                v01 = 0.5f * v01 * (1.0f + erff(v01 * 0.70710678118654752f));
                v10 = 0.5f * v10 * (1.0f + erff(v10 * 0.70710678118654752f));
                v11 = 0.5f * v11 * (1.0f + erff(v11 * 0.70710678118654752f));
                int nw = N >> 1;
                C16[(size_t)r0 * nw + (col >> 1)]       = packh2(v00, v01);
                C16[(size_t)(r0 + 8) * nw + (col >> 1)] = packh2(v10, v11);
            } else if (EPI == 3) {
                unsigned* o = (blockIdx.z == 0) ? (unsigned*)Cv : (unsigned*)C1f;
                int nw = N >> 1;
                o[(size_t)r0 * nw + (col >> 1)]       = packh2(v00, v01);
                o[(size_t)(r0 + 8) * nw + (col >> 1)] = packh2(v10, v11);
            } else {
                size_t o0 = (size_t)r0 * N + col;
                size_t o1 = (size_t)(r0 + 8) * N + col;
                if (EPI == 1) {
                    float2 c0 = *(const float2*)(Cin + o0);
                    float2 c1 = *(const float2*)(Cin + o1);
                    v00 += c0.x; v01 += c0.y; v10 += c1.x; v11 += c1.y;
                }
                if (!NG) {
                    *(float2*)(Cf + o0) = make_float2(v00, v01);
                    *(float2*)(Cf + o1) = make_float2(v10, v11);
                } else {
                    // N odd (head gemm): scalar stores only.
                    if (col < N)     { Cf[o0] = v00;     Cf[o1] = v10; }
                    if (col + 1 < N) { Cf[o0 + 1] = v01; Cf[o1 + 1] = v11; }
                }
            }
        }
    }
}

// ---------------- embedding ----------------
__global__ void embed_kernel(const int* __restrict__ idx,
                             const float* __restrict__ wte,
                             const float* __restrict__ wpe,
                             float* __restrict__ x)
{
    int row = blockIdx.x;
    int s   = row & (SS - 1);
    int tok = idx[row];
    int tid = threadIdx.x;
    #pragma unroll
    for (int l = 0; l < 3; l++) {
        int d = tid + l * 256;
        x[(size_t)row * DD + d] = wte[(size_t)tok * DD + d] + wpe[(size_t)s * DD + d];
    }
}

// ---------------- layernorm -> packed fp16 (shuffle reductions) ------------
__global__ void layernorm_kernel(const float* __restrict__ x,
                                 const float* __restrict__ w,
                                 const float* __restrict__ b,
                                 unsigned* __restrict__ y16)
{
    int row = blockIdx.x;
    const float2* p2 = (const float2*)(x + (size_t)row * DD);
    int tid = threadIdx.x;                 // 256
    int lane = tid & 31, wid = tid >> 5;
    float2 f1 = p2[tid];
    float2 f2 = (tid < 128) ? p2[tid + 256] : make_float2(0.f, 0.f);

    __shared__ float ws[8], ws2[8];
    float s = f1.x + f1.y + f2.x + f2.y;
    #pragma unroll
    for (int o = 16; o > 0; o >>= 1) s += __shfl_xor_sync(0xffffffffu, s, o);
    if (lane == 0) ws[wid] = s;
    __syncthreads();
    float mean = (ws[0] + ws[1] + ws[2] + ws[3] + ws[4] + ws[5] + ws[6] + ws[7])
                 * (1.0f / DD);

    float a0 = f1.x - mean, a1 = f1.y - mean;
    float a2 = f2.x - mean, a3 = f2.y - mean;
    float sq = a0 * a0 + a1 * a1 + ((tid < 128) ? (a2 * a2 + a3 * a3) : 0.f);
    #pragma unroll
    for (int o = 16; o > 0; o >>= 1) sq += __shfl_xor_sync(0xffffffffu, sq, o);
    if (lane == 0) ws2[wid] = sq;
    __syncthreads();
    float var = (ws2[0] + ws2[1] + ws2[2] + ws2[3] + ws2[4] + ws2[5] + ws2[6] + ws2[7])
                * (1.0f / DD);
    float rstd = rsqrtf(var + 1e-5f);

    const float2* w2 = (const float2*)w;
    const float2* b2 = (const float2*)b;
    unsigned* yr = y16 + (size_t)row * KPD;
    {
        float2 ww = w2[tid], bb = b2[tid];
        yr[tid] = packh2(a0 * rstd * ww.x + bb.x, a1 * rstd * ww.y + bb.y);
    }
    if (tid < 128) {
        float2 ww = w2[tid + 256], bb = b2[tid + 256];
        yr[tid + 256] = packh2(a2 * rstd * ww.x + bb.x, a3 * rstd * ww.y + bb.y);
    }
}

// ---------------- fused flash attention (fp16, double-buffered KV) ---------
#define FST 36
#define FQW (64 * FST)
#define FBW (3 * 64 * FST)
#define FA_SMEM_BYTES ((FQW + 2 * FBW) * 4)   // 64512

__global__ __launch_bounds__(128, 3)
void flash_attn_kernel(const unsigned* __restrict__ q16,
                       const unsigned* __restrict__ k16,
                       const unsigned* __restrict__ vph,
                       const unsigned* __restrict__ vpl,
                       unsigned* __restrict__ O16)
{
    extern __shared__ unsigned fsm[];

    const int tid  = threadIdx.x;
    const int lane = tid & 31;
    const int w    = tid >> 5;
    const int lr   = lane >> 2;
    const int lq   = lane & 3;
    const int it   = (SS / 64 - 1) - blockIdx.x;
    const int bh   = blockIdx.y;
    const int b    = bh / HH, h = bh % HH;
    const int i0   = it * 64;
    const int lrow = lane & 7, lg = lane >> 3;

    const uint32_t sQb = smem_u32(fsm);
    const uint32_t aoff = (uint32_t)(((w * 16 + (lg & 1) * 8 + lrow) * FST
                                      + (lg >> 1) * 4) * 4);
    const uint32_t boff = (uint32_t)((((lg >> 1) * 8 + lrow) * FST
                                      + (lg & 1) * 4) * 4);

    auto load_tile = [&](int j0, int buf) {
        const uint32_t kb  = sQb + (uint32_t)(FQW + buf * FBW) * 4u;
        const uint32_t vhb = kb + (uint32_t)(64 * FST) * 4u;
        const uint32_t vlb = vhb + (uint32_t)(64 * FST) * 4u;
        #pragma unroll
        for (int p = 0; p < 4; p++) {
            int s = tid + p * 128;
            int r = s >> 3, c4 = (s & 7) * 4;
            cp16(kb + (uint32_t)(r * FST + c4) * 4u,
                 k16 + (size_t)(b * SS + j0 + r) * KPD + h * 32 + c4);
            size_t vo = ((size_t)bh * DKK + r) * (SS / 2) + (j0 >> 1) + c4;
            cp16(vhb + (uint32_t)(r * FST + c4) * 4u, vph + vo);
            cp16(vlb + (uint32_t)(r * FST + c4) * 4u, vpl + vo);
        }
        asm volatile("cp.async.commit_group;" ::: "memory");
    };

    #pragma unroll
    for (int p = 0; p < 4; p++) {
        int s = tid + p * 128;
        int r = s >> 3, c4 = (s & 7) * 4;
        cp16(sQb + (uint32_t)(r * FST + c4) * 4u,
             q16 + (size_t)(b * SS + i0 + r) * KPD + h * 32 + c4);
    }
    asm volatile("cp.async.commit_group;" ::: "memory");
    load_tile(0, 0);
    asm volatile("cp.async.wait_group 1;" ::: "memory");
    __syncthreads();

    unsigned qf[4][4];
    #pragma unroll
    for (int kc = 0; kc < 4; kc++)
        LDSM4(qf[kc][0], qf[kc][1], qf[kc][2], qf[kc][3], sQb + aoff + kc * 32);

    float oacc[8][4];
    #pragma unroll
    for (int nt = 0; nt < 8; nt++)
        #pragma unroll
        for (int e = 0; e < 4; e++) oacc[nt][e] = 0.0f;
    float m0 = -1e30f, m1 = -1e30f, l0 = 0.0f, l1 = 0.0f;

    int buf = 0;
    for (int j0 = 0; j0 <= i0; j0 += 64) {
        __syncthreads();
        const bool more = (j0 + 64 <= i0);
        if (more) load_tile(j0 + 64, buf ^ 1);
        if (more) asm volatile("cp.async.wait_group 1;" ::: "memory");
        else      asm volatile("cp.async.wait_group 0;" ::: "memory");
        __syncthreads();

        const uint32_t kb  = sQb + (uint32_t)(FQW + buf * FBW) * 4u;
        const uint32_t vhb = kb + (uint32_t)(64 * FST) * 4u;
        const uint32_t vlb = vhb + (uint32_t)(64 * FST) * 4u;

        float sacc[8][4];
        #pragma unroll
        for (int nt = 0; nt < 8; nt++)
            #pragma unroll
            for (int e = 0; e < 4; e++) sacc[nt][e] = 0.0f;
        #pragma unroll
        for (int kc = 0; kc < 4; kc++) {
            #pragma unroll
            for (int nb = 0; nb < 4; nb++) {
                unsigned r0, r1, r2, r3;
                LDSM4(r0, r1, r2, r3,
                      kb + boff + (uint32_t)(nb * 16 * FST * 4) + kc * 32);
                unsigned b0[2] = {r0, r1}, b1[2] = {r2, r3};
                mma16(sacc[nb * 2],     qf[kc], b0);
                mma16(sacc[nb * 2 + 1], qf[kc], b1);
            }
        }

        #pragma unroll
        for (int nt = 0; nt < 8; nt++)
            #pragma unroll
            for (int e = 0; e < 4; e++) sacc[nt][e] *= 0.125f;
        if (j0 == i0) {
            int ii0 = w * 16 + lr, ii1 = ii0 + 8;
            #pragma unroll
            for (int nt = 0; nt < 8; nt++) {
                int jj = nt * 8 + 2 * lq;
                if (jj     > ii0) sacc[nt][0] = -1e30f;
                if (jj + 1 > ii0) sacc[nt][1] = -1e30f;
                if (jj     > ii1) sacc[nt][2] = -1e30f;
                if (jj + 1 > ii1) sacc[nt][3] = -1e30f;
            }
        }

        float rm0 = -1e30f, rm1 = -1e30f;
        #pragma unroll
        for (int nt = 0; nt < 8; nt++) {
            rm0 = fmaxf(rm0, fmaxf(sacc[nt][0], sacc[nt][1]));
            rm1 = fmaxf(rm1, fmaxf(sacc[nt][2], sacc[nt][3]));
        }
        rm0 = fmaxf(rm0, __shfl_xor_sync(0xffffffffu, rm0, 1));
        rm0 = fmaxf(rm0, __shfl_xor_sync(0xffffffffu, rm0, 2));
        rm1 = fmaxf(rm1, __shfl_xor_sync(0xffffffffu, rm1, 1));
        rm1 = fmaxf(rm1, __shfl_xor_sync(0xffffffffu, rm1, 2));
        float mn0 = fmaxf(m0, rm0), mn1 = fmaxf(m1, rm1);
        float f0 = __expf(m0 - mn0), f1 = __expf(m1 - mn1);
        float ps0 = 0.0f, ps1 = 0.0f;
        #pragma unroll
        for (int nt = 0; nt < 8; nt++) {
            float p0 = __expf(sacc[nt][0] - mn0); sacc[nt][0] = p0; ps0 += p0;
            float p1 = __expf(sacc[nt][1] - mn0); sacc[nt][1] = p1; ps0 += p1;
            float p2 = __expf(sacc[nt][2] - mn1); sacc[nt][2] = p2; ps1 += p2;
            float p3 = __expf(sacc[nt][3] - mn1); sacc[nt][3] = p3; ps1 += p3;
        }
        ps0 += __shfl_xor_sync(0xffffffffu, ps0, 1);
        ps0 += __shfl_xor_sync(0xffffffffu, ps0, 2);
        ps1 += __shfl_xor_sync(0xffffffffu, ps1, 1);
        ps1 += __shfl_xor_sync(0xffffffffu, ps1, 2);
        l0 = l0 * f0 + ps0;
        l1 = l1 * f1 + ps1;
        m0 = mn0; m1 = mn1;
        #pragma unroll
        for (int nt = 0; nt < 8; nt++) {
            oacc[nt][0] *= f0; oacc[nt][1] *= f0;
            oacc[nt][2] *= f1; oacc[nt][3] *= f1;
        }

        #pragma unroll
        for (int kc = 0; kc < 4; kc++) {
            unsigned ah[4], al[4];
            #pragma unroll
            for (int hsel = 0; hsel < 2; hsel++) {
                const float* s0 = sacc[2 * kc + hsel];
                unsigned hi0 = packh2(s0[0], s0[1]);
                unsigned hi1 = packh2(s0[2], s0[3]);
                __half2 h2a = *reinterpret_cast<__half2*>(&hi0);
                __half2 h2b = *reinterpret_cast<__half2*>(&hi1);
                float2 fa = __half22float2(h2a);
                float2 fb = __half22float2(h2b);
                ah[hsel * 2]     = hi0;
                ah[hsel * 2 + 1] = hi1;
                al[hsel * 2]     = packh2(s0[0] - fa.x, s0[1] - fa.y);
                al[hsel * 2 + 1] = packh2(s0[2] - fb.x, s0[3] - fb.y);
            }
            #pragma unroll
            for (int nb = 0; nb < 4; nb++) {
                uint32_t va = boff + (uint32_t)(nb * 16 * FST * 4) + kc * 32;
                unsigned h0, h1, h2, h3, g0, g1, g2, g3;
                LDSM4(h0, h1, h2, h3, vhb + va);
                LDSM4(g0, g1, g2, g3, vlb + va);
                unsigned bh0[2] = {h0, h1}, bh1[2] = {h2, h3};
                unsigned bl0[2] = {g0, g1}, bl1[2] = {g2, g3};
                mma16(oacc[nb * 2],     ah, bh0);
                mma16(oacc[nb * 2],     al, bh0);
                mma16(oacc[nb * 2],     ah, bl0);
                mma16(oacc[nb * 2 + 1], ah, bh1);
                mma16(oacc[nb * 2 + 1], al, bh1);
                mma16(oacc[nb * 2 + 1], ah, bl1);
            }
        }
        buf ^= 1;
    }

    float inv0 = 1.0f / l0, inv1 = 1.0f / l1;
    int row0 = b * SS + i0 + w * 16 + lr;
    unsigned* Ob = O16 + (size_t)row0 * KPD + h * 32;
    #pragma unroll
    for (int nt = 0; nt < 8; nt++) {
        Ob[nt * 4 + lq] = packh2(oacc[nt][0] * inv0, oacc[nt][1] * inv0);
        Ob[(size_t)8 * KPD + nt * 4 + lq] = packh2(oacc[nt][2] * inv1, oacc[nt][3] * inv1);
    }
}

// ---------------- host launcher ----------------
extern "C" void kernel_launch(void* const* d_in, const int* in_sizes, int n_in,
                              void* d_out, int out_size)
{
    const int*   idx   = (const int*)  d_in[0];
    const float* wte   = (const float*)d_in[1];
    const float* wpe   = (const float*)d_in[2];
    const float* ln1_w = (const float*)d_in[3];
    const float* ln1_b = (const float*)d_in[4];
    const float* wq    = (const float*)d_in[5];
    const float* wk    = (const float*)d_in[6];
    const float* wv    = (const float*)d_in[7];
    const float* wo    = (const float*)d_in[8];
    const float* ln2_w = (const float*)d_in[9];
    const float* ln2_b = (const float*)d_in[10];
    const float* fc1   = (const float*)d_in[11];
    const float* fc2   = (const float*)d_in[12];
    const float* lnf_w = (const float*)d_in[13];
    const float* lnf_b = (const float*)d_in[14];
    float* out = (float*)d_out;

    float *x;
    unsigned *q16, *k16, *h16, *tmp16, *ff16, *vph, *vpl;
    unsigned *wq16, *wk16, *wv16, *wo16, *fc116, *fc216, *wte16;
    cudaGetSymbolAddress((void**)&x,     g_x);
    cudaGetSymbolAddress((void**)&q16,   g_q16);
    cudaGetSymbolAddress((void**)&k16,   g_k16);
    cudaGetSymbolAddress((void**)&h16,   g_h16);
    cudaGetSymbolAddress((void**)&tmp16, g_tmp16);
    cudaGetSymbolAddress((void**)&ff16,  g_ff16);
    cudaGetSymbolAddress((void**)&vph,   g_vph);
    cudaGetSymbolAddress((void**)&vpl,   g_vpl);
    cudaGetSymbolAddress((void**)&wq16,  g_wq16);
    cudaGetSymbolAddress((void**)&wk16,  g_wk16);
    cudaGetSymbolAddress((void**)&wv16,  g_wv16);
    cudaGetSymbolAddress((void**)&wo16,  g_wo16);
    cudaGetSymbolAddress((void**)&fc116, g_fc116);
    cudaGetSymbolAddress((void**)&fc216, g_fc216);
    cudaGetSymbolAddress((void**)&wte16, g_wte16);

    const int gs128 = 3 * (256 * APAD) * 4;    // 110592 bytes
    const int gs64  = 3 * (192 * APAD) * 4;    // 82944 bytes
    cudaFuncSetAttribute((const void*)mma_gemm<1,false,128,false>,
                         cudaFuncAttributeMaxDynamicSharedMemorySize, gs128);
    cudaFuncSetAttribute((const void*)mma_gemm<2,false,128,false>,
                         cudaFuncAttributeMaxDynamicSharedMemorySize, gs128);
    cudaFuncSetAttribute((const void*)mma_gemm<3,false,128,false>,
                         cudaFuncAttributeMaxDynamicSharedMemorySize, gs128);
    cudaFuncSetAttribute((const void*)mma_gemm<0,true,128,true>,
                         cudaFuncAttributeMaxDynamicSharedMemorySize, gs128);
    cudaFuncSetAttribute((const void*)mma_gemm<1,false,64,false>,
                         cudaFuncAttributeMaxDynamicSharedMemorySize, gs64);
    cudaFuncSetAttribute((const void*)flash_attn_kernel,
                         cudaFuncAttributeMaxDynamicSharedMemorySize, FA_SMEM_BYTES);

    pack_t<<<dim3(DD / 64, DD / 64, LL), 256>>>(wq, wq16, DD, DD);
    pack_t<<<dim3(DD / 64, DD / 64, LL), 256>>>(wk, wk16, DD, DD);
    pack_t<<<dim3(DD / 64, DD / 64, LL), 256>>>(wv, wv16, DD, DD);
    pack_t<<<dim3(DD / 64, DD / 64, LL), 256>>>(wo, wo16, DD, DD);
    pack_t<<<dim3(DFF / 64, DD / 64, LL), 256>>>(fc1, fc116, DD, DFF);
    pack_t<<<dim3(DD / 64, DFF / 64, LL), 256>>>(fc2, fc216, DFF, DD);
    {
        int t2 = VV * KPD / 2;                  // uint2 count
        pack_nk<<<(t2 + 255) / 256, 256>>>(wte, wte16, t2);
    }

    embed_kernel<<<NTOK, 256>>>(idx, wte, wpe, x);

    dim3 gQKV(DD / 128, NTOK / 128, 3);
    dim3 gD64(DD / 128, NTOK / 64, 1);      // (6, 64) for wo / fc2
    dim3 gF  (DFF / 128, NTOK / 128, 1);

    for (int l = 0; l < LL; l++) {
        unsigned* Wq = wq16 + (size_t)l * DD * KPD;
        unsigned* Wk = wk16 + (size_t)l * DD * KPD;
        unsigned* Wv = wv16 + (size_t)l * DD * KPD;
        unsigned* Wo = wo16 + (size_t)l * DD * KPD;
        unsigned* W1 = fc116 + (size_t)l * DFF * KPD;
        unsigned* W2 = fc216 + (size_t)l * DD * KPF;

        layernorm_kernel<<<NTOK, 256>>>(x, ln1_w + l * DD, ln1_b + l * DD, h16);

        // q -> q16, k -> k16, v -> fused transpose into vph/vpl
        mma_gemm<3,false,128,false><<<gQKV, 256, gs128>>>(
            h16, Wq, Wk, Wv, nullptr, q16, (float*)k16, vph, vpl, DD, DD);

        flash_attn_kernel<<<dim3(SS / 64, BB * HH), 128, FA_SMEM_BYTES>>>(
            q16, k16, vph, vpl, tmp16);

        mma_gemm<1,false,64,false><<<gD64, 256, gs64>>>(
            tmp16, Wo, Wo, Wo, x, x, nullptr, nullptr, nullptr, DD, DD);

        layernorm_kernel<<<NTOK, 256>>>(x, ln2_w + l * DD, ln2_b + l * DD, h16);
        mma_gemm<2,false,128,false><<<gF, 256, gs128>>>(
            h16, W1, W1, W1, nullptr, ff16, nullptr, nullptr, nullptr, DFF, DD);
        mma_gemm<1,false,64,false><<<gD64, 256, gs64>>>(
            ff16, W2, W2, W2, x, x, nullptr, nullptr, nullptr, DD, DFF);
    }

    layernorm_kernel<<<NTOK, 256>>>(x, lnf_w, lnf_b, h16);
    // head gemm: grid axes swapped (M fastest) so concurrent CTAs share B tiles
    // in L2; B DRAM traffic drops ~32x.
    mma_gemm<0,true,128,true><<<dim3(NTOK / 128, (VV + 127) / 128, 1), 256, gs128>>>(
        h16, wte16, wte16, wte16, nullptr, out, nullptr, nullptr, nullptr, VV, DD);
}